// round 1
// baseline (speedup 1.0000x reference)
#include <cuda_runtime.h>
#include <math.h>
#include <stdint.h>

// ---------------------------------------------------------------------------
// Problem constants
// ---------------------------------------------------------------------------
#define B_   4
#define N_   1024
#define D_   1024
#define H_   16
#define HD_  64
#define COND_ 256
#define BN_  (B_ * N_)        // 4096 rows
#define M2_  (2 * N_)         // 2048 memory tokens
#define ADA_COLS 9216         // first 9 of 12 D-chunks of ada

// ---------------------------------------------------------------------------
// Scratch (single static device buffer; no allocations anywhere)
// ---------------------------------------------------------------------------
static const size_t OFF_ADA   = 0;                          // [4096, 9216]
static const size_t OFF_XN    = OFF_ADA   + 37748736UL;     // [4096, 1024]
static const size_t OFF_QKV   = OFF_XN    + 4194304UL;      // [4096, 3072] (reused: qc pre-rope)
static const size_t OFF_Q     = OFF_QKV   + 12582912UL;     // [B,H,N,64]
static const size_t OFF_K     = OFF_Q     + 4194304UL;
static const size_t OFF_V     = OFF_K     + 4194304UL;
static const size_t OFF_ATTN  = OFF_V     + 4194304UL;      // [4096, 1024]
static const size_t OFF_PROJ  = OFF_ATTN  + 4194304UL;      // [4096, 1024]
static const size_t OFF_X     = OFF_PROJ  + 4194304UL;      // residual stream
static const size_t OFF_MEMLN = OFF_X     + 4194304UL;      // [8192, 1024]
static const size_t OFF_KV    = OFF_MEMLN + 8388608UL;      // [8192, 2048]
static const size_t OFF_QC    = OFF_KV    + 16777216UL;     // [B,H,N,64]
static const size_t OFF_KC    = OFF_QC    + 4194304UL;      // [B,H,2N,64]
static const size_t OFF_VC    = OFF_KC    + 8388608UL;      // [B,H,2N,64]
static const size_t OFF_H     = OFF_VC    + 8388608UL;      // [4096, 4096]
static const size_t SCRATCH_TOTAL = OFF_H + 16777216UL;     // 142,606,336 floats

__device__ float g_buf[SCRATCH_TOTAL];

// ---------------------------------------------------------------------------
// GELU (tanh approx, matches jax.nn.gelu approximate=True)
// ---------------------------------------------------------------------------
__device__ __forceinline__ float gelu_tanh(float x) {
    float x3 = x * x * x;
    return 0.5f * x * (1.0f + tanhf(0.7978845608028654f * (x + 0.044715f * x3)));
}

// ---------------------------------------------------------------------------
// Tiled fp32 GEMM:  C[M, Ncols] = A[M, K] @ W[Ncols, K]^T   (NT, both K-major)
// 128x128 tile, BK=16, 256 threads, 8x8 per thread.
// ---------------------------------------------------------------------------
#define BM 128
#define BN 128
#define BK 16

template<int DO_BIAS, int DO_GELU>
__global__ void __launch_bounds__(256)
sgemm_nt(const float* __restrict__ A, const float* __restrict__ W,
         const float* __restrict__ bias, float* __restrict__ C,
         int M, int Ncols, int K) {
    __shared__ __align__(16) float As[BK][BM + 4];
    __shared__ __align__(16) float Ws[BK][BN + 4];

    const int tid = threadIdx.x;
    const int tx  = tid & 15;    // N direction (8 cols each)
    const int ty  = tid >> 4;    // M direction (8 rows each)

    const float* Ab = A + (size_t)(blockIdx.y) * BM * K;
    const float* Wb = W + (size_t)(blockIdx.x) * BN * K;

    const int lrow = tid >> 2;          // 0..63
    const int lcol = (tid & 3) * 4;     // 0,4,8,12

    float acc[8][8];
#pragma unroll
    for (int i = 0; i < 8; i++)
#pragma unroll
        for (int j = 0; j < 8; j++) acc[i][j] = 0.0f;

    for (int k0 = 0; k0 < K; k0 += BK) {
#pragma unroll
        for (int r = 0; r < 2; r++) {
            int row = lrow + r * 64;
            float4 va = *reinterpret_cast<const float4*>(Ab + (size_t)row * K + k0 + lcol);
            As[lcol + 0][row] = va.x; As[lcol + 1][row] = va.y;
            As[lcol + 2][row] = va.z; As[lcol + 3][row] = va.w;
            float4 vw = *reinterpret_cast<const float4*>(Wb + (size_t)row * K + k0 + lcol);
            Ws[lcol + 0][row] = vw.x; Ws[lcol + 1][row] = vw.y;
            Ws[lcol + 2][row] = vw.z; Ws[lcol + 3][row] = vw.w;
        }
        __syncthreads();

#pragma unroll
        for (int kk = 0; kk < BK; kk++) {
            float a[8], b[8];
            float4 a0 = *reinterpret_cast<const float4*>(&As[kk][ty * 8]);
            float4 a1 = *reinterpret_cast<const float4*>(&As[kk][ty * 8 + 4]);
            a[0] = a0.x; a[1] = a0.y; a[2] = a0.z; a[3] = a0.w;
            a[4] = a1.x; a[5] = a1.y; a[6] = a1.z; a[7] = a1.w;
            float4 b0 = *reinterpret_cast<const float4*>(&Ws[kk][tx * 8]);
            float4 b1 = *reinterpret_cast<const float4*>(&Ws[kk][tx * 8 + 4]);
            b[0] = b0.x; b[1] = b0.y; b[2] = b0.z; b[3] = b0.w;
            b[4] = b1.x; b[5] = b1.y; b[6] = b1.z; b[7] = b1.w;
#pragma unroll
            for (int i = 0; i < 8; i++)
#pragma unroll
                for (int j = 0; j < 8; j++)
                    acc[i][j] = fmaf(a[i], b[j], acc[i][j]);
        }
        __syncthreads();
    }

    const int crow = blockIdx.y * BM + ty * 8;
    const int ccol = blockIdx.x * BN + tx * 8;
#pragma unroll
    for (int i = 0; i < 8; i++) {
#pragma unroll
        for (int j = 0; j < 8; j++) {
            float v = acc[i][j];
            if (DO_BIAS) v += bias[ccol + j];
            if (DO_GELU) v = gelu_tanh(v);
            C[(size_t)(crow + i) * Ncols + ccol + j] = v;
        }
    }
}

// ---------------------------------------------------------------------------
// LayerNorm (+optional adaLN modulate). One block (256 thr) per row of D=1024.
// sh/sc point into the ada buffer at stride ADA_COLS (or nullptr).
// ---------------------------------------------------------------------------
__global__ void __launch_bounds__(256)
ln_mod_kernel(const float* __restrict__ x, const float* __restrict__ w,
              const float* __restrict__ sh, const float* __restrict__ sc,
              float* __restrict__ out) {
    __shared__ float rbuf[64];
    const int row = blockIdx.x;
    const int t = threadIdx.x;
    const float* xr = x + (size_t)row * D_;

    float vals[4];
    float sum = 0.f, sq = 0.f;
#pragma unroll
    for (int i = 0; i < 4; i++) {
        float v = xr[t + 256 * i];
        vals[i] = v;
        sum += v;
        sq  += v * v;
    }
    for (int o = 16; o; o >>= 1) {
        sum += __shfl_xor_sync(0xffffffffu, sum, o);
        sq  += __shfl_xor_sync(0xffffffffu, sq, o);
    }
    if ((t & 31) == 0) { rbuf[t >> 5] = sum; rbuf[(t >> 5) + 32] = sq; }
    __syncthreads();
    if (t == 0) {
        float s = 0.f, q = 0.f;
        for (int i = 0; i < 8; i++) { s += rbuf[i]; q += rbuf[i + 32]; }
        float mean = s * (1.0f / D_);
        float var  = q * (1.0f / D_) - mean * mean;
        rbuf[0] = mean;
        rbuf[1] = rsqrtf(var + 1e-5f);
    }
    __syncthreads();
    float mean = rbuf[0], inv = rbuf[1];

    const size_t mbase = (size_t)row * ADA_COLS;
    float* orow = out + (size_t)row * D_;
#pragma unroll
    for (int i = 0; i < 4; i++) {
        int col = t + 256 * i;
        float xn = (vals[i] - mean) * inv * w[col];
        if (sh != nullptr) {
            xn = xn * (1.0f + sc[mbase + col]) + sh[mbase + col];
        }
        orow[col] = xn;
    }
}

// ---------------------------------------------------------------------------
// Memory assembly + LayerNorm: rows 0..2N-1 per batch pick h_content / h_obs.
// ---------------------------------------------------------------------------
__global__ void __launch_bounds__(256)
memln_kernel(const float* __restrict__ h_content, const float* __restrict__ h_obs,
             const float* __restrict__ w, float* __restrict__ out) {
    __shared__ float rbuf[64];
    const int row = blockIdx.x;            // 0..8191
    const int t = threadIdx.x;
    const int b = row >> 11;
    const int m = row & 2047;
    const float* xr = (m < N_)
        ? h_content + ((size_t)b * N_ + m) * D_
        : h_obs     + ((size_t)b * N_ + (m - N_)) * D_;

    float vals[4];
    float sum = 0.f, sq = 0.f;
#pragma unroll
    for (int i = 0; i < 4; i++) {
        float v = xr[t + 256 * i];
        vals[i] = v; sum += v; sq += v * v;
    }
    for (int o = 16; o; o >>= 1) {
        sum += __shfl_xor_sync(0xffffffffu, sum, o);
        sq  += __shfl_xor_sync(0xffffffffu, sq, o);
    }
    if ((t & 31) == 0) { rbuf[t >> 5] = sum; rbuf[(t >> 5) + 32] = sq; }
    __syncthreads();
    if (t == 0) {
        float s = 0.f, q = 0.f;
        for (int i = 0; i < 8; i++) { s += rbuf[i]; q += rbuf[i + 32]; }
        float mean = s * (1.0f / D_);
        float var  = q * (1.0f / D_) - mean * mean;
        rbuf[0] = mean; rbuf[1] = rsqrtf(var + 1e-5f);
    }
    __syncthreads();
    float mean = rbuf[0], inv = rbuf[1];
    float* orow = out + (size_t)row * D_;
#pragma unroll
    for (int i = 0; i < 4; i++) {
        int col = t + 256 * i;
        orow[col] = (vals[i] - mean) * inv * w[col];
    }
}

// ---------------------------------------------------------------------------
// RoPE helpers. rotate_half(x)[d] = d<32 ? -x[d+32] : x[d-32]; partner = d^32.
// ---------------------------------------------------------------------------
__global__ void rope_split_qkv(const float* __restrict__ qkv,
                               const float* __restrict__ cosb, const float* __restrict__ sinb,
                               float* __restrict__ q, float* __restrict__ k,
                               float* __restrict__ v) {
    int idx = blockIdx.x * blockDim.x + threadIdx.x;   // B*N*H*HD = 4,194,304
    int d = idx & 63;
    int h = (idx >> 6) & 15;
    int n = (idx >> 10) & 1023;
    int b = idx >> 20;
    const float* row = qkv + (size_t)(b * N_ + n) * 3072;
    float c = cosb[n * 64 + d], s = sinb[n * 64 + d];
    int off = h * 64 + d;
    int poff = h * 64 + (d ^ 32);
    float sgn = (d < 32) ? -1.0f : 1.0f;
    float qv = row[off],        qp = row[poff];
    float kv = row[1024 + off], kp = row[1024 + poff];
    float vv = row[2048 + off];
    size_t o = (((size_t)(b * H_ + h)) * N_ + n) * 64 + d;
    q[o] = qv * c + sgn * qp * s;
    k[o] = kv * c + sgn * kp * s;
    v[o] = vv;
}

__global__ void rope_q_kernel(const float* __restrict__ qin,
                              const float* __restrict__ cosb, const float* __restrict__ sinb,
                              float* __restrict__ q) {
    int idx = blockIdx.x * blockDim.x + threadIdx.x;   // 4,194,304
    int d = idx & 63;
    int h = (idx >> 6) & 15;
    int n = (idx >> 10) & 1023;
    int b = idx >> 20;
    const float* row = qin + (size_t)(b * N_ + n) * D_;
    float c = cosb[n * 64 + d], s = sinb[n * 64 + d];
    float sgn = (d < 32) ? -1.0f : 1.0f;
    float x  = row[h * 64 + d];
    float xp = row[h * 64 + (d ^ 32)];
    q[(((size_t)(b * H_ + h)) * N_ + n) * 64 + d] = x * c + sgn * xp * s;
}

__global__ void rope_split_kv(const float* __restrict__ kv,
                              const float* __restrict__ cosb, const float* __restrict__ sinb,
                              float* __restrict__ k, float* __restrict__ v) {
    int idx = blockIdx.x * blockDim.x + threadIdx.x;   // B*2N*H*HD = 8,388,608
    int d = idx & 63;
    int h = (idx >> 6) & 15;
    int m = (idx >> 10) & 2047;
    int b = idx >> 21;
    const float* row = kv + (size_t)(b * M2_ + m) * 2048;
    int pos = m & 1023;                                 // same cos/sin for both halves
    float c = cosb[pos * 64 + d], s = sinb[pos * 64 + d];
    float sgn = (d < 32) ? -1.0f : 1.0f;
    float kx  = row[h * 64 + d];
    float kp  = row[h * 64 + (d ^ 32)];
    float vx  = row[1024 + h * 64 + d];
    size_t o = (((size_t)(b * H_ + h)) * M2_ + m) * 64 + d;
    k[o] = kx * c + sgn * kp * s;
    v[o] = vx;
}

// ---------------------------------------------------------------------------
// Attention: one block (128 thr) per (b, h, q). Full score row in smem.
// q,k,v: [B, H, Nk, 64]. mask: [B, Nq, Nk]. out: [B, Nq, H*64].
// ---------------------------------------------------------------------------
__global__ void __launch_bounds__(128)
attn_kernel(const float* __restrict__ q, const float* __restrict__ k,
            const float* __restrict__ v, const float* __restrict__ mask,
            float* __restrict__ out, int Nq, int Nk) {
    extern __shared__ float sm[];
    float* qv  = sm;            // 64
    float* sc  = sm + 64;       // Nk
    float* red = sm + 64 + Nk;  // 32

    const int t = threadIdx.x;
    const int qi = blockIdx.x, h = blockIdx.y, b = blockIdx.z;

    const float* qp = q + ((((size_t)b * H_ + h) * Nq + qi) << 6);
    if (t < 64) qv[t] = qp[t];
    __syncthreads();

    const float* kb = k + (((size_t)b * H_ + h) * Nk << 6);
    const float* vb = v + (((size_t)b * H_ + h) * Nk << 6);
    const float* mrow = mask + ((size_t)b * Nq + qi) * (size_t)Nk;

    float lmax = -3.0e38f;
    for (int j = t; j < Nk; j += 128) {
        const float4* kr = reinterpret_cast<const float4*>(kb + ((size_t)j << 6));
        float s = 0.f;
#pragma unroll
        for (int u = 0; u < 16; u++) {
            float4 k4 = kr[u];
            s = fmaf(qv[4 * u + 0], k4.x, s);
            s = fmaf(qv[4 * u + 1], k4.y, s);
            s = fmaf(qv[4 * u + 2], k4.z, s);
            s = fmaf(qv[4 * u + 3], k4.w, s);
        }
        s = s * 0.125f + mrow[j];
        sc[j] = s;
        lmax = fmaxf(lmax, s);
    }
    for (int o = 16; o; o >>= 1) lmax = fmaxf(lmax, __shfl_xor_sync(0xffffffffu, lmax, o));
    if ((t & 31) == 0) red[t >> 5] = lmax;
    __syncthreads();
    float mx = fmaxf(fmaxf(red[0], red[1]), fmaxf(red[2], red[3]));

    float lsum = 0.f;
    for (int j = t; j < Nk; j += 128) {
        float p = __expf(sc[j] - mx);
        sc[j] = p;
        lsum += p;
    }
    for (int o = 16; o; o >>= 1) lsum += __shfl_xor_sync(0xffffffffu, lsum, o);
    __syncthreads();                       // red reuse + all sc[] visible after next sync
    if ((t & 31) == 0) red[t >> 5] = lsum;
    __syncthreads();
    float ssum = red[0] + red[1] + red[2] + red[3];

    const int d = t & 63, half = t >> 6;
    const int jb = half * (Nk >> 1), je = jb + (Nk >> 1);
    float acc = 0.f;
    for (int j = jb; j < je; j++) acc = fmaf(sc[j], vb[((size_t)j << 6) + d], acc);
    __syncthreads();
    if (half) qv[d] = acc;
    __syncthreads();
    if (!half)
        out[((size_t)b * Nq + qi) * 1024 + h * 64 + d] = (acc + qv[d]) / ssum;
}

// ---------------------------------------------------------------------------
// Residual + adaLN gate: out = xr + g * c   (g at chunk offset, stride 9216)
// ---------------------------------------------------------------------------
__global__ void resid_gate_kernel(const float* __restrict__ xr,
                                  const float* __restrict__ gbase,
                                  const float* __restrict__ c,
                                  float* __restrict__ out) {
    int idx = blockIdx.x * blockDim.x + threadIdx.x;  // 4,194,304
    int row = idx >> 10, col = idx & 1023;
    out[idx] = xr[idx] + gbase[(size_t)row * ADA_COLS + col] * c[idx];
}

// ---------------------------------------------------------------------------
// kernel_launch
// ---------------------------------------------------------------------------
extern "C" void kernel_launch(void* const* d_in, const int* in_sizes, int n_in,
                              void* d_out, int out_size) {
    (void)in_sizes; (void)n_in; (void)out_size;
    const float* q_x        = (const float*)d_in[0];
    const float* h_content  = (const float*)d_in[1];
    const float* h_obs      = (const float*)d_in[2];
    const float* t_cond     = (const float*)d_in[3];
    const float* cosb       = (const float*)d_in[4];
    const float* sinb       = (const float*)d_in[5];
    const float* M_QQ       = (const float*)d_in[6];
    const float* M_hyb      = (const float*)d_in[7];
    const float* w_ln_self  = (const float*)d_in[8];
    const float* w_qkv      = (const float*)d_in[9];
    const float* w_self_out = (const float*)d_in[10];
    const float* w_ln_cross = (const float*)d_in[11];
    const float* w_ln_mem   = (const float*)d_in[12];
    const float* w_qproj    = (const float*)d_in[13];
    const float* w_kvproj   = (const float*)d_in[14];
    const float* w_cross_out= (const float*)d_in[15];
    const float* w_ln_mlp   = (const float*)d_in[16];
    const float* w_mlp1     = (const float*)d_in[17];
    const float* b_mlp1     = (const float*)d_in[18];
    const float* w_mlp2     = (const float*)d_in[19];
    const float* b_mlp2     = (const float*)d_in[20];
    const float* w_ada      = (const float*)d_in[21];
    const float* b_ada      = (const float*)d_in[22];
    float* out = (float*)d_out;

    float* S = nullptr;
    cudaGetSymbolAddress((void**)&S, g_buf);
    float* ADA   = S + OFF_ADA;
    float* XN    = S + OFF_XN;
    float* QKV   = S + OFF_QKV;
    float* Q     = S + OFF_Q;
    float* K     = S + OFF_K;
    float* V     = S + OFF_V;
    float* ATTN  = S + OFF_ATTN;
    float* PROJ  = S + OFF_PROJ;
    float* X     = S + OFF_X;
    float* MEMLN = S + OFF_MEMLN;
    float* KV    = S + OFF_KV;
    float* QC    = S + OFF_QC;
    float* KC    = S + OFF_KC;
    float* VC    = S + OFF_VC;
    float* HBUF  = S + OFF_H;

    // ada = t_cond @ w_ada[:9216].T + b_ada[:9216]   -> [4096, 9216]
    sgemm_nt<1, 0><<<dim3(ADA_COLS / BN, BN_ / BM), 256>>>(
        t_cond, w_ada, b_ada, ADA, BN_, ADA_COLS, COND_);

    // ---- Pass 1: self-attention ----
    ln_mod_kernel<<<BN_, 256>>>(q_x, w_ln_self, ADA + 0 * D_, ADA + 1 * D_, XN);
    sgemm_nt<0, 0><<<dim3(3072 / BN, BN_ / BM), 256>>>(XN, w_qkv, nullptr, QKV, BN_, 3072, D_);
    rope_split_qkv<<<4194304 / 256, 256>>>(QKV, cosb, sinb, Q, K, V);
    attn_kernel<<<dim3(N_, H_, B_), 128, (64 + N_ + 32) * sizeof(float)>>>(
        Q, K, V, M_QQ, ATTN, N_, N_);
    sgemm_nt<0, 0><<<dim3(D_ / BN, BN_ / BM), 256>>>(ATTN, w_self_out, nullptr, PROJ, BN_, D_, D_);
    resid_gate_kernel<<<4194304 / 256, 256>>>(q_x, ADA + 2 * D_, PROJ, X);

    // ---- Pass 2: cross-attention ----
    ln_mod_kernel<<<BN_, 256>>>(X, w_ln_cross, ADA + 3 * D_, ADA + 4 * D_, XN);
    sgemm_nt<0, 0><<<dim3(D_ / BN, BN_ / BM), 256>>>(XN, w_qproj, nullptr, QKV, BN_, D_, D_);
    rope_q_kernel<<<4194304 / 256, 256>>>(QKV, cosb, sinb, QC);
    memln_kernel<<<B_ * M2_, 256>>>(h_content, h_obs, w_ln_mem, MEMLN);
    sgemm_nt<0, 0><<<dim3(2048 / BN, (B_ * M2_) / BM), 256>>>(
        MEMLN, w_kvproj, nullptr, KV, B_ * M2_, 2048, D_);
    rope_split_kv<<<8388608 / 256, 256>>>(KV, cosb, sinb, KC, VC);
    attn_kernel<<<dim3(N_, H_, B_), 128, (64 + M2_ + 32) * sizeof(float)>>>(
        QC, KC, VC, M_hyb, ATTN, N_, M2_);
    sgemm_nt<0, 0><<<dim3(D_ / BN, BN_ / BM), 256>>>(ATTN, w_cross_out, nullptr, PROJ, BN_, D_, D_);
    resid_gate_kernel<<<4194304 / 256, 256>>>(X, ADA + 5 * D_, PROJ, X);

    // ---- Pass 3: MLP ----
    ln_mod_kernel<<<BN_, 256>>>(X, w_ln_mlp, ADA + 6 * D_, ADA + 7 * D_, XN);
    sgemm_nt<1, 1><<<dim3(4096 / BN, BN_ / BM), 256>>>(XN, w_mlp1, b_mlp1, HBUF, BN_, 4096, D_);
    sgemm_nt<1, 0><<<dim3(D_ / BN, BN_ / BM), 256>>>(HBUF, w_mlp2, b_mlp2, PROJ, BN_, D_, 4096);
    resid_gate_kernel<<<4194304 / 256, 256>>>(X, ADA + 8 * D_, PROJ, out);
}

// round 3
// speedup vs baseline: 6.1121x; 6.1121x over previous
#include <cuda_runtime.h>
#include <math.h>
#include <stdint.h>

// ---------------------------------------------------------------------------
// Problem constants
// ---------------------------------------------------------------------------
#define B_   4
#define N_   1024
#define D_   1024
#define H_   16
#define HD_  64
#define COND_ 256
#define BN_  (B_ * N_)        // 4096 rows
#define M2_  (2 * N_)         // 2048 memory tokens
#define ADA_COLS 9216         // first 9 of 12 D-chunks of ada

// ---------------------------------------------------------------------------
// Scratch (single static device buffer; no allocations anywhere).
// NOTE: SC (attention scores) aliases HBUF (MLP hidden): SC is dead before
// the MLP pass writes HBUF, so they share the same region.
// ---------------------------------------------------------------------------
static const size_t OFF_ADA   = 0;                          // [4096, 9216]
static const size_t OFF_XN    = OFF_ADA   + 37748736UL;     // [4096, 1024]
static const size_t OFF_QKV   = OFF_XN    + 4194304UL;      // [4096, 3072]
static const size_t OFF_Q     = OFF_QKV   + 12582912UL;     // [B,H,N,64]
static const size_t OFF_K     = OFF_Q     + 4194304UL;
static const size_t OFF_V     = OFF_K     + 4194304UL;
static const size_t OFF_ATTN  = OFF_V     + 4194304UL;      // [4096, 1024]
static const size_t OFF_PROJ  = OFF_ATTN  + 4194304UL;      // [4096, 1024]
static const size_t OFF_X     = OFF_PROJ  + 4194304UL;      // residual stream
static const size_t OFF_MEMLN = OFF_X     + 4194304UL;      // [8192, 1024]
static const size_t OFF_KV    = OFF_MEMLN + 8388608UL;      // [8192, 2048]
static const size_t OFF_QC    = OFF_KV    + 16777216UL;     // [B,H,N,64]
static const size_t OFF_KC    = OFF_QC    + 4194304UL;      // [B,H,2N,64]
static const size_t OFF_VC    = OFF_KC    + 8388608UL;      // [B,H,2N,64]
static const size_t OFF_H     = OFF_VC    + 8388608UL;      // [4096,4096] MLP hidden
static const size_t OFF_SC    = OFF_H;                      // [B,H,N,2N] scores (aliases HBUF)
static const size_t SCRATCH_TOTAL = OFF_SC + 134217728UL;   // ~1.04 GB fp32

__device__ float g_buf[SCRATCH_TOTAL];

// ---------------------------------------------------------------------------
// Helpers
// ---------------------------------------------------------------------------
__device__ __forceinline__ float gelu_tanh(float x) {
    float x3 = x * x * x;
    return 0.5f * x * (1.0f + tanhf(0.7978845608028654f * (x + 0.044715f * x3)));
}

__device__ __forceinline__ uint32_t f2tf(float x) {
    uint32_t r;
    asm("cvt.rna.tf32.f32 %0, %1;" : "=r"(r) : "f"(x));
    return r;
}

__device__ __forceinline__ void mma8(float c[4], const uint32_t a[4], const uint32_t b[2]) {
    asm volatile(
        "mma.sync.aligned.m16n8k8.row.col.f32.tf32.tf32.f32 "
        "{%0,%1,%2,%3}, {%4,%5,%6,%7}, {%8,%9}, {%0,%1,%2,%3};\n"
        : "+f"(c[0]), "+f"(c[1]), "+f"(c[2]), "+f"(c[3])
        : "r"(a[0]), "r"(a[1]), "r"(a[2]), "r"(a[3]), "r"(b[0]), "r"(b[1]));
}

// ---------------------------------------------------------------------------
// TF32 tensor-core GEMM.
//   C = A @ B^T   (TRB=1, B stored [Ncols, K] row-major)
//   C = A @ B     (TRB=0, B stored [K, Ncols] row-major, ld = auxld)
// Batched over blockIdx.z with two-part strides (zb = z/16, zh = z%16).
// EPI: 0 none, 1 +bias[col], 2 gelu(v+bias[col]), 3 v*scale + mask (ld=auxld).
// BM x BN x 32 tile, 256 threads (4x2 warps), warp tile (BM/4)x(BN/2).
// ---------------------------------------------------------------------------
#define EPI_NONE 0
#define EPI_BIAS 1
#define EPI_GELU 2
#define EPI_MASK 3

template<int BM, int BN, int TRB, int EPI>
__global__ void __launch_bounds__(256)
mm_tf32(const float* __restrict__ A, const float* __restrict__ Bmat,
        const float* __restrict__ aux, float* __restrict__ C,
        int K, int auxld, int ldC,
        long long sAb, long long sAh, long long sBb, long long sBh,
        long long sCb, long long sCh, long long sMb, float scale) {
    constexpr int BK  = 32;
    constexpr int WM  = BM / 4;
    constexpr int WN  = BN / 2;
    constexpr int MT  = WM / 16;
    constexpr int NTN = WN / 8;
    constexpr int AI  = (BM * BK) / 1024;   // float4 loads per thread for A
    constexpr int BI  = (BN * BK) / 1024;

    __shared__ float As[BM][BK + 4];
    __shared__ float Ws[BN][BK + 4];

    const int tid  = threadIdx.x;
    const int wid  = tid >> 5, lane = tid & 31;
    const int wm   = wid >> 1, wn   = wid & 1;
    const int gid  = lane >> 2, tig = lane & 3;
    const int z    = blockIdx.z;
    const int zb   = z >> 4, zh = z & 15;

    const float* Ab = A + sAb * zb + sAh * zh + (size_t)blockIdx.y * BM * K;
    const float* Bb = Bmat + sBb * zb + sBh * zh;
    if (TRB) Bb += (size_t)blockIdx.x * BN * K;
    else     Bb += blockIdx.x * BN;
    float* Cb = C + sCb * zb + sCh * zh;

    float acc[MT][NTN][4];
#pragma unroll
    for (int mt = 0; mt < MT; mt++)
#pragma unroll
        for (int nt = 0; nt < NTN; nt++)
#pragma unroll
            for (int i = 0; i < 4; i++) acc[mt][nt][i] = 0.0f;

    float4 apf[AI], bpf[BI];

    // ---- prefetch helpers ----
    auto loadA = [&](int k0) {
#pragma unroll
        for (int i = 0; i < AI; i++) {
            int flat = i * 256 + tid;
            int row = flat >> 3, c4 = (flat & 7) << 2;
            apf[i] = *reinterpret_cast<const float4*>(Ab + (size_t)row * K + k0 + c4);
        }
    };
    auto loadB = [&](int k0) {
#pragma unroll
        for (int i = 0; i < BI; i++) {
            int flat = i * 256 + tid;
            if (TRB) {
                int row = flat >> 3, c4 = (flat & 7) << 2;
                bpf[i] = *reinterpret_cast<const float4*>(Bb + (size_t)row * K + k0 + c4);
            } else {
                int kr = flat / (BN / 4), c4 = (flat % (BN / 4)) << 2;
                bpf[i] = *reinterpret_cast<const float4*>(Bb + (size_t)(k0 + kr) * auxld + c4);
            }
        }
    };
    auto stores = [&]() {
#pragma unroll
        for (int i = 0; i < AI; i++) {
            int flat = i * 256 + tid;
            int row = flat >> 3, c4 = (flat & 7) << 2;
            As[row][c4 + 0] = __uint_as_float(f2tf(apf[i].x));
            As[row][c4 + 1] = __uint_as_float(f2tf(apf[i].y));
            As[row][c4 + 2] = __uint_as_float(f2tf(apf[i].z));
            As[row][c4 + 3] = __uint_as_float(f2tf(apf[i].w));
        }
#pragma unroll
        for (int i = 0; i < BI; i++) {
            int flat = i * 256 + tid;
            if (TRB) {
                int row = flat >> 3, c4 = (flat & 7) << 2;
                Ws[row][c4 + 0] = __uint_as_float(f2tf(bpf[i].x));
                Ws[row][c4 + 1] = __uint_as_float(f2tf(bpf[i].y));
                Ws[row][c4 + 2] = __uint_as_float(f2tf(bpf[i].z));
                Ws[row][c4 + 3] = __uint_as_float(f2tf(bpf[i].w));
            } else {
                int kr = flat / (BN / 4), c4 = (flat % (BN / 4)) << 2;
                Ws[c4 + 0][kr] = __uint_as_float(f2tf(bpf[i].x));
                Ws[c4 + 1][kr] = __uint_as_float(f2tf(bpf[i].y));
                Ws[c4 + 2][kr] = __uint_as_float(f2tf(bpf[i].z));
                Ws[c4 + 3][kr] = __uint_as_float(f2tf(bpf[i].w));
            }
        }
    };

    loadA(0); loadB(0);
    const int nkt = K / BK;
    for (int kt = 0; kt < nkt; kt++) {
        stores();
        __syncthreads();
        if (kt + 1 < nkt) { loadA((kt + 1) * BK); loadB((kt + 1) * BK); }

#pragma unroll
        for (int ks = 0; ks < BK; ks += 8) {
            uint32_t af[MT][4], bf[NTN][2];
#pragma unroll
            for (int mt = 0; mt < MT; mt++) {
                int m0 = wm * WM + mt * 16 + gid;
                af[mt][0] = __float_as_uint(As[m0][ks + tig]);
                af[mt][1] = __float_as_uint(As[m0 + 8][ks + tig]);
                af[mt][2] = __float_as_uint(As[m0][ks + tig + 4]);
                af[mt][3] = __float_as_uint(As[m0 + 8][ks + tig + 4]);
            }
#pragma unroll
            for (int nt = 0; nt < NTN; nt++) {
                int n0 = wn * WN + nt * 8 + gid;
                bf[nt][0] = __float_as_uint(Ws[n0][ks + tig]);
                bf[nt][1] = __float_as_uint(Ws[n0][ks + tig + 4]);
            }
#pragma unroll
            for (int mt = 0; mt < MT; mt++)
#pragma unroll
                for (int nt = 0; nt < NTN; nt++)
                    mma8(acc[mt][nt], af[mt], bf[nt]);
        }
        __syncthreads();
    }

    // ---- epilogue ----
    const int brow = blockIdx.y * BM;
    const int bcol = blockIdx.x * BN;
#pragma unroll
    for (int mt = 0; mt < MT; mt++) {
#pragma unroll
        for (int nt = 0; nt < NTN; nt++) {
            int r0  = brow + wm * WM + mt * 16 + gid;
            int col = bcol + wn * WN + nt * 8 + tig * 2;
            float v0 = acc[mt][nt][0], v1 = acc[mt][nt][1];
            float v2 = acc[mt][nt][2], v3 = acc[mt][nt][3];
            if (EPI == EPI_BIAS) {
                float b0 = aux[col], b1 = aux[col + 1];
                v0 += b0; v1 += b1; v2 += b0; v3 += b1;
            } else if (EPI == EPI_GELU) {
                float b0 = aux[col], b1 = aux[col + 1];
                v0 = gelu_tanh(v0 + b0); v1 = gelu_tanh(v1 + b1);
                v2 = gelu_tanh(v2 + b0); v3 = gelu_tanh(v3 + b1);
            } else if (EPI == EPI_MASK) {
                const float* mb = aux + sMb * zb;
                v0 = v0 * scale + mb[(size_t)r0 * auxld + col];
                v1 = v1 * scale + mb[(size_t)r0 * auxld + col + 1];
                v2 = v2 * scale + mb[(size_t)(r0 + 8) * auxld + col];
                v3 = v3 * scale + mb[(size_t)(r0 + 8) * auxld + col + 1];
            }
            *reinterpret_cast<float2*>(Cb + (size_t)r0 * ldC + col)       = make_float2(v0, v1);
            *reinterpret_cast<float2*>(Cb + (size_t)(r0 + 8) * ldC + col) = make_float2(v2, v3);
        }
    }
}

// ---------------------------------------------------------------------------
// Row softmax over pre-masked scores. One block (256 thr) per row.
// Nk in {1024, 2048}; values held in registers (<=8 per thread).
// ---------------------------------------------------------------------------
__global__ void __launch_bounds__(256)
softmax_rows(float* __restrict__ sc, int Nk) {
    float* r = sc + (size_t)blockIdx.x * Nk;
    const int t = threadIdx.x;
    __shared__ float red[8];

    float v[8];
    const int per = Nk >> 8;   // 4 or 8
    float lmax = -3.0e38f;
    for (int i = 0; i < per; i++) {
        v[i] = r[t + (i << 8)];
        lmax = fmaxf(lmax, v[i]);
    }
    for (int o = 16; o; o >>= 1) lmax = fmaxf(lmax, __shfl_xor_sync(0xffffffffu, lmax, o));
    if ((t & 31) == 0) red[t >> 5] = lmax;
    __syncthreads();
    float mx = red[0];
#pragma unroll
    for (int i = 1; i < 8; i++) mx = fmaxf(mx, red[i]);
    __syncthreads();

    float lsum = 0.f;
    for (int i = 0; i < per; i++) {
        v[i] = __expf(v[i] - mx);
        lsum += v[i];
    }
    for (int o = 16; o; o >>= 1) lsum += __shfl_xor_sync(0xffffffffu, lsum, o);
    if ((t & 31) == 0) red[t >> 5] = lsum;
    __syncthreads();
    float s = 0.f;
#pragma unroll
    for (int i = 0; i < 8; i++) s += red[i];
    float inv = 1.0f / s;
    for (int i = 0; i < per; i++) r[t + (i << 8)] = v[i] * inv;
}

// ---------------------------------------------------------------------------
// LayerNorm (+optional adaLN modulate). One block (256 thr) per row of D=1024.
// ---------------------------------------------------------------------------
__global__ void __launch_bounds__(256)
ln_mod_kernel(const float* __restrict__ x, const float* __restrict__ w,
              const float* __restrict__ sh, const float* __restrict__ sc,
              float* __restrict__ out) {
    __shared__ float rbuf[64];
    const int row = blockIdx.x;
    const int t = threadIdx.x;
    const float* xr = x + (size_t)row * D_;

    float vals[4];
    float sum = 0.f, sq = 0.f;
#pragma unroll
    for (int i = 0; i < 4; i++) {
        float v = xr[t + 256 * i];
        vals[i] = v; sum += v; sq += v * v;
    }
    for (int o = 16; o; o >>= 1) {
        sum += __shfl_xor_sync(0xffffffffu, sum, o);
        sq  += __shfl_xor_sync(0xffffffffu, sq, o);
    }
    if ((t & 31) == 0) { rbuf[t >> 5] = sum; rbuf[(t >> 5) + 32] = sq; }
    __syncthreads();
    if (t == 0) {
        float s = 0.f, q = 0.f;
        for (int i = 0; i < 8; i++) { s += rbuf[i]; q += rbuf[i + 32]; }
        float mean = s * (1.0f / D_);
        float var  = q * (1.0f / D_) - mean * mean;
        rbuf[0] = mean; rbuf[1] = rsqrtf(var + 1e-5f);
    }
    __syncthreads();
    float mean = rbuf[0], inv = rbuf[1];

    const size_t mbase = (size_t)row * ADA_COLS;
    float* orow = out + (size_t)row * D_;
#pragma unroll
    for (int i = 0; i < 4; i++) {
        int col = t + 256 * i;
        float xn = (vals[i] - mean) * inv * w[col];
        if (sh != nullptr) xn = xn * (1.0f + sc[mbase + col]) + sh[mbase + col];
        orow[col] = xn;
    }
}

// ---------------------------------------------------------------------------
// Memory assembly + LayerNorm (rows pick h_content / h_obs)
// ---------------------------------------------------------------------------
__global__ void __launch_bounds__(256)
memln_kernel(const float* __restrict__ h_content, const float* __restrict__ h_obs,
             const float* __restrict__ w, float* __restrict__ out) {
    __shared__ float rbuf[64];
    const int row = blockIdx.x;            // 0..8191
    const int t = threadIdx.x;
    const int b = row >> 11;
    const int m = row & 2047;
    const float* xr = (m < N_)
        ? h_content + ((size_t)b * N_ + m) * D_
        : h_obs     + ((size_t)b * N_ + (m - N_)) * D_;

    float vals[4];
    float sum = 0.f, sq = 0.f;
#pragma unroll
    for (int i = 0; i < 4; i++) {
        float v = xr[t + 256 * i];
        vals[i] = v; sum += v; sq += v * v;
    }
    for (int o = 16; o; o >>= 1) {
        sum += __shfl_xor_sync(0xffffffffu, sum, o);
        sq  += __shfl_xor_sync(0xffffffffu, sq, o);
    }
    if ((t & 31) == 0) { rbuf[t >> 5] = sum; rbuf[(t >> 5) + 32] = sq; }
    __syncthreads();
    if (t == 0) {
        float s = 0.f, q = 0.f;
        for (int i = 0; i < 8; i++) { s += rbuf[i]; q += rbuf[i + 32]; }
        float mean = s * (1.0f / D_);
        float var  = q * (1.0f / D_) - mean * mean;
        rbuf[0] = mean; rbuf[1] = rsqrtf(var + 1e-5f);
    }
    __syncthreads();
    float mean = rbuf[0], inv = rbuf[1];
    float* orow = out + (size_t)row * D_;
#pragma unroll
    for (int i = 0; i < 4; i++) {
        int col = t + 256 * i;
        orow[col] = (vals[i] - mean) * inv * w[col];
    }
}

// ---------------------------------------------------------------------------
// RoPE helpers. rotate_half partner = d^32, sign = (d<32) ? -1 : +1.
// ---------------------------------------------------------------------------
__global__ void rope_split_qkv(const float* __restrict__ qkv,
                               const float* __restrict__ cosb, const float* __restrict__ sinb,
                               float* __restrict__ q, float* __restrict__ k,
                               float* __restrict__ v) {
    int idx = blockIdx.x * blockDim.x + threadIdx.x;   // 4,194,304
    int d = idx & 63;
    int h = (idx >> 6) & 15;
    int n = (idx >> 10) & 1023;
    int b = idx >> 20;
    const float* row = qkv + (size_t)(b * N_ + n) * 3072;
    float c = cosb[n * 64 + d], s = sinb[n * 64 + d];
    int off = h * 64 + d;
    int poff = h * 64 + (d ^ 32);
    float sgn = (d < 32) ? -1.0f : 1.0f;
    float qv = row[off],        qp = row[poff];
    float kv = row[1024 + off], kp = row[1024 + poff];
    float vv = row[2048 + off];
    size_t o = (((size_t)(b * H_ + h)) * N_ + n) * 64 + d;
    q[o] = qv * c + sgn * qp * s;
    k[o] = kv * c + sgn * kp * s;
    v[o] = vv;
}

__global__ void rope_q_kernel(const float* __restrict__ qin,
                              const float* __restrict__ cosb, const float* __restrict__ sinb,
                              float* __restrict__ q) {
    int idx = blockIdx.x * blockDim.x + threadIdx.x;   // 4,194,304
    int d = idx & 63;
    int h = (idx >> 6) & 15;
    int n = (idx >> 10) & 1023;
    int b = idx >> 20;
    const float* row = qin + (size_t)(b * N_ + n) * D_;
    float c = cosb[n * 64 + d], s = sinb[n * 64 + d];
    float sgn = (d < 32) ? -1.0f : 1.0f;
    float x  = row[h * 64 + d];
    float xp = row[h * 64 + (d ^ 32)];
    q[(((size_t)(b * H_ + h)) * N_ + n) * 64 + d] = x * c + sgn * xp * s;
}

__global__ void rope_split_kv(const float* __restrict__ kv,
                              const float* __restrict__ cosb, const float* __restrict__ sinb,
                              float* __restrict__ k, float* __restrict__ v) {
    int idx = blockIdx.x * blockDim.x + threadIdx.x;   // 8,388,608
    int d = idx & 63;
    int h = (idx >> 6) & 15;
    int m = (idx >> 10) & 2047;
    int b = idx >> 21;
    const float* row = kv + (size_t)(b * M2_ + m) * 2048;
    int pos = m & 1023;
    float c = cosb[pos * 64 + d], s = sinb[pos * 64 + d];
    float sgn = (d < 32) ? -1.0f : 1.0f;
    float kx  = row[h * 64 + d];
    float kp  = row[h * 64 + (d ^ 32)];
    float vx  = row[1024 + h * 64 + d];
    size_t o = (((size_t)(b * H_ + h)) * M2_ + m) * 64 + d;
    k[o] = kx * c + sgn * kp * s;
    v[o] = vx;
}

// ---------------------------------------------------------------------------
// Residual + adaLN gate: out = xr + g * c
// ---------------------------------------------------------------------------
__global__ void resid_gate_kernel(const float* __restrict__ xr,
                                  const float* __restrict__ gbase,
                                  const float* __restrict__ c,
                                  float* __restrict__ out) {
    int idx = blockIdx.x * blockDim.x + threadIdx.x;  // 4,194,304
    int row = idx >> 10, col = idx & 1023;
    out[idx] = xr[idx] + gbase[(size_t)row * ADA_COLS + col] * c[idx];
}

// ---------------------------------------------------------------------------
// kernel_launch
// ---------------------------------------------------------------------------
extern "C" void kernel_launch(void* const* d_in, const int* in_sizes, int n_in,
                              void* d_out, int out_size) {
    (void)in_sizes; (void)n_in; (void)out_size;
    const float* q_x        = (const float*)d_in[0];
    const float* h_content  = (const float*)d_in[1];
    const float* h_obs      = (const float*)d_in[2];
    const float* t_cond     = (const float*)d_in[3];
    const float* cosb       = (const float*)d_in[4];
    const float* sinb       = (const float*)d_in[5];
    const float* M_QQ       = (const float*)d_in[6];
    const float* M_hyb      = (const float*)d_in[7];
    const float* w_ln_self  = (const float*)d_in[8];
    const float* w_qkv      = (const float*)d_in[9];
    const float* w_self_out = (const float*)d_in[10];
    const float* w_ln_cross = (const float*)d_in[11];
    const float* w_ln_mem   = (const float*)d_in[12];
    const float* w_qproj    = (const float*)d_in[13];
    const float* w_kvproj   = (const float*)d_in[14];
    const float* w_cross_out= (const float*)d_in[15];
    const float* w_ln_mlp   = (const float*)d_in[16];
    const float* w_mlp1     = (const float*)d_in[17];
    const float* b_mlp1     = (const float*)d_in[18];
    const float* w_mlp2     = (const float*)d_in[19];
    const float* b_mlp2     = (const float*)d_in[20];
    const float* w_ada      = (const float*)d_in[21];
    const float* b_ada      = (const float*)d_in[22];
    float* out = (float*)d_out;

    float* S = nullptr;
    cudaGetSymbolAddress((void**)&S, g_buf);
    float* ADA   = S + OFF_ADA;
    float* XN    = S + OFF_XN;
    float* QKV   = S + OFF_QKV;
    float* Q     = S + OFF_Q;
    float* K     = S + OFF_K;
    float* V     = S + OFF_V;
    float* ATTN  = S + OFF_ATTN;
    float* PROJ  = S + OFF_PROJ;
    float* X     = S + OFF_X;
    float* MEMLN = S + OFF_MEMLN;
    float* KV    = S + OFF_KV;
    float* QC    = S + OFF_QC;
    float* KC    = S + OFF_KC;
    float* VC    = S + OFF_VC;
    float* HBUF  = S + OFF_H;
    float* SC    = S + OFF_SC;

    const long long NQNK1 = (long long)N_ * N_;       // 1M
    const long long NQNK2 = (long long)N_ * M2_;      // 2M
    const long long QH    = (long long)N_ * 64;       // per-head Q/K/V slab
    const long long KH2   = (long long)M2_ * 64;

    // ada = t_cond @ w_ada[:9216].T + b_ada
    mm_tf32<128, 128, 1, EPI_BIAS><<<dim3(72, 32, 1), 256>>>(
        t_cond, w_ada, b_ada, ADA, COND_, 0, ADA_COLS, 0, 0, 0, 0, 0, 0, 0, 1.f);

    // ---- Pass 1: self-attention ----
    ln_mod_kernel<<<BN_, 256>>>(q_x, w_ln_self, ADA + 0 * D_, ADA + 1 * D_, XN);
    mm_tf32<128, 128, 1, EPI_NONE><<<dim3(24, 32, 1), 256>>>(
        XN, w_qkv, nullptr, QKV, D_, 0, 3072, 0, 0, 0, 0, 0, 0, 0, 1.f);
    rope_split_qkv<<<4194304 / 256, 256>>>(QKV, cosb, sinb, Q, K, V);
    // scores = Q @ K^T * 0.125 + mask
    mm_tf32<128, 128, 1, EPI_MASK><<<dim3(8, 8, 64), 256>>>(
        Q, K, M_QQ, SC, 64, N_, N_,
        16 * QH, QH, 16 * QH, QH, 16 * NQNK1, NQNK1, NQNK1, 0.125f);
    softmax_rows<<<B_ * H_ * N_, 256>>>(SC, N_);
    // attn = P @ V
    mm_tf32<128, 64, 0, EPI_NONE><<<dim3(1, 8, 64), 256>>>(
        SC, V, nullptr, ATTN, N_, 64, D_,
        16 * NQNK1, NQNK1, 16 * QH, QH, (long long)N_ * D_, 64, 0, 1.f);
    mm_tf32<128, 128, 1, EPI_NONE><<<dim3(8, 32, 1), 256>>>(
        ATTN, w_self_out, nullptr, PROJ, D_, 0, D_, 0, 0, 0, 0, 0, 0, 0, 1.f);
    resid_gate_kernel<<<4194304 / 256, 256>>>(q_x, ADA + 2 * D_, PROJ, X);

    // ---- Pass 2: cross-attention ----
    ln_mod_kernel<<<BN_, 256>>>(X, w_ln_cross, ADA + 3 * D_, ADA + 4 * D_, XN);
    mm_tf32<128, 128, 1, EPI_NONE><<<dim3(8, 32, 1), 256>>>(
        XN, w_qproj, nullptr, QKV, D_, 0, D_, 0, 0, 0, 0, 0, 0, 0, 1.f);
    rope_q_kernel<<<4194304 / 256, 256>>>(QKV, cosb, sinb, QC);
    memln_kernel<<<B_ * M2_, 256>>>(h_content, h_obs, w_ln_mem, MEMLN);
    mm_tf32<128, 128, 1, EPI_NONE><<<dim3(16, 64, 1), 256>>>(
        MEMLN, w_kvproj, nullptr, KV, D_, 0, 2048, 0, 0, 0, 0, 0, 0, 0, 1.f);
    rope_split_kv<<<8388608 / 256, 256>>>(KV, cosb, sinb, KC, VC);
    mm_tf32<128, 128, 1, EPI_MASK><<<dim3(16, 8, 64), 256>>>(
        QC, KC, M_hyb, SC, 64, M2_, M2_,
        16 * QH, QH, 16 * KH2, KH2, 16 * NQNK2, NQNK2, NQNK2, 0.125f);
    softmax_rows<<<B_ * H_ * N_, 256>>>(SC, M2_);
    mm_tf32<128, 64, 0, EPI_NONE><<<dim3(1, 8, 64), 256>>>(
        SC, VC, nullptr, ATTN, M2_, 64, D_,
        16 * NQNK2, NQNK2, 16 * KH2, KH2, (long long)N_ * D_, 64, 0, 1.f);
    mm_tf32<128, 128, 1, EPI_NONE><<<dim3(8, 32, 1), 256>>>(
        ATTN, w_cross_out, nullptr, PROJ, D_, 0, D_, 0, 0, 0, 0, 0, 0, 0, 1.f);
    resid_gate_kernel<<<4194304 / 256, 256>>>(X, ADA + 5 * D_, PROJ, X);

    // ---- Pass 3: MLP (HBUF aliases SC — scores are dead by now) ----
    ln_mod_kernel<<<BN_, 256>>>(X, w_ln_mlp, ADA + 6 * D_, ADA + 7 * D_, XN);
    mm_tf32<128, 128, 1, EPI_GELU><<<dim3(32, 32, 1), 256>>>(
        XN, w_mlp1, b_mlp1, HBUF, D_, 0, 4096, 0, 0, 0, 0, 0, 0, 0, 1.f);
    mm_tf32<128, 128, 1, EPI_BIAS><<<dim3(8, 32, 1), 256>>>(
        HBUF, w_mlp2, b_mlp2, PROJ, 4096, 0, D_, 0, 0, 0, 0, 0, 0, 0, 1.f);
    resid_gate_kernel<<<4194304 / 256, 256>>>(X, ADA + 8 * D_, PROJ, out);
}

// round 5
// speedup vs baseline: 8.3513x; 1.3663x over previous
#include <cuda_runtime.h>
#include <math.h>
#include <stdint.h>

// ---------------------------------------------------------------------------
// Problem constants
// ---------------------------------------------------------------------------
#define B_   4
#define N_   1024
#define D_   1024
#define H_   16
#define COND_ 256
#define BN_  (B_ * N_)        // 4096 rows
#define M2_  (2 * N_)         // 2048 memory tokens
#define ADA_COLS 9216         // first 9 of 12 D-chunks of ada

// ---------------------------------------------------------------------------
// Scratch (single static device buffer; no allocations anywhere)
// ---------------------------------------------------------------------------
static const size_t OFF_ADA   = 0;                          // [4096, 9216]
static const size_t OFF_XN    = OFF_ADA   + 37748736UL;     // [4096, 1024]
static const size_t OFF_QKV   = OFF_XN    + 4194304UL;      // [4096, 3072]
static const size_t OFF_Q     = OFF_QKV   + 12582912UL;     // [B,H,N,64]
static const size_t OFF_K     = OFF_Q     + 4194304UL;
static const size_t OFF_V     = OFF_K     + 4194304UL;
static const size_t OFF_ATTN  = OFF_V     + 4194304UL;      // [4096, 1024]
static const size_t OFF_PROJ  = OFF_ATTN  + 4194304UL;      // [4096, 1024]
static const size_t OFF_X     = OFF_PROJ  + 4194304UL;      // residual stream
static const size_t OFF_MEMLN = OFF_X     + 4194304UL;      // [8192, 1024]
static const size_t OFF_KV    = OFF_MEMLN + 8388608UL;      // [8192, 2048]
static const size_t OFF_QC    = OFF_KV    + 16777216UL;     // [B,H,N,64]
static const size_t OFF_KC    = OFF_QC    + 4194304UL;      // [B,H,2N,64]
static const size_t OFF_VC    = OFF_KC    + 8388608UL;      // [B,H,2N,64]
static const size_t OFF_H     = OFF_VC    + 8388608UL;      // [4096,4096] MLP hidden
static const size_t SCRATCH_TOTAL = OFF_H + 16777216UL;

__device__ float g_buf[SCRATCH_TOTAL];

// ---------------------------------------------------------------------------
// Helpers
// ---------------------------------------------------------------------------
__device__ __forceinline__ float gelu_tanh(float x) {
    float x3 = x * x * x;
    return 0.5f * x * (1.0f + tanhf(0.7978845608028654f * (x + 0.044715f * x3)));
}

// tf32 mma, fp32 accumulate. Raw fp32 in registers: HW reads top 19 bits
// (RZ truncation) — acceptable vs 1e-3 budget.
__device__ __forceinline__ void mma8(float c[4], const uint32_t a[4], const uint32_t b[2]) {
    asm volatile(
        "mma.sync.aligned.m16n8k8.row.col.f32.tf32.tf32.f32 "
        "{%0,%1,%2,%3}, {%4,%5,%6,%7}, {%8,%9}, {%0,%1,%2,%3};\n"
        : "+f"(c[0]), "+f"(c[1]), "+f"(c[2]), "+f"(c[3])
        : "r"(a[0]), "r"(a[1]), "r"(a[2]), "r"(a[3]), "r"(b[0]), "r"(b[1]));
}

__device__ __forceinline__ void cp16(uint32_t saddr, const void* gptr) {
    asm volatile("cp.async.ca.shared.global [%0], [%1], 16;\n" :: "r"(saddr), "l"(gptr));
}

// ---------------------------------------------------------------------------
// TF32 GEMM: C[M,Ncols] = A[M,K] @ W[Ncols,K]^T, 3-stage cp.async pipeline.
// 128x128x32 tile, 256 threads (4x2 warps), warp tile 32x64.
// smem: 2 * 3 * 128 * 36 floats = 110,592 B (dynamic).
// ---------------------------------------------------------------------------
#define EPI_NONE 0
#define EPI_BIAS 1
#define EPI_GELU 2
#define MM_SMEM (2 * 3 * 128 * 36 * 4)

template<int EPI>
__global__ void __launch_bounds__(256, 2)
mm_tf32(const float* __restrict__ A, const float* __restrict__ W,
        const float* __restrict__ bias, float* __restrict__ C,
        int K, int Ncols) {
    extern __shared__ float sm[];
    float* AsB = sm;                 // [3][128][36]
    float* WsB = sm + 3 * 128 * 36;

    const int tid  = threadIdx.x;
    const int wid  = tid >> 5, lane = tid & 31;
    const int wm   = wid >> 1, wn   = wid & 1;
    const int gid  = lane >> 2, tig = lane & 3;
    const int lrow = tid >> 3;          // 0..31
    const int lcol = (tid & 7) << 2;    // 0,4,..,28

    const float* Ab = A + (size_t)blockIdx.y * 128 * K;
    const float* Wb = W + (size_t)blockIdx.x * 128 * K;

    const uint32_t asb = (uint32_t)__cvta_generic_to_shared(AsB);
    const uint32_t wsb = (uint32_t)__cvta_generic_to_shared(WsB);

    auto issue = [&](int st, int kt) {
        const int k0 = kt * 32;
        const uint32_t sst = (uint32_t)(st * 128 * 36) * 4;
#pragma unroll
        for (int i = 0; i < 4; i++) {
            int r = lrow + i * 32;
            uint32_t so = sst + (uint32_t)(r * 36 + lcol) * 4;
            cp16(asb + so, Ab + (size_t)r * K + k0 + lcol);
            cp16(wsb + so, Wb + (size_t)r * K + k0 + lcol);
        }
        asm volatile("cp.async.commit_group;\n");
    };

    float acc[2][8][4];
#pragma unroll
    for (int mt = 0; mt < 2; mt++)
#pragma unroll
        for (int nt = 0; nt < 8; nt++)
#pragma unroll
            for (int i = 0; i < 4; i++) acc[mt][nt][i] = 0.0f;

    const int nkt = K / 32;
    issue(0, 0);
    issue(1, 1);

    for (int kt = 0; kt < nkt; kt++) {
        asm volatile("cp.async.wait_group 1;\n");
        __syncthreads();
        const int nk = kt + 2;
        if (nk < nkt) issue(nk % 3, nk);

        const float* as = AsB + (kt % 3) * 128 * 36;
        const float* ws = WsB + (kt % 3) * 128 * 36;
#pragma unroll
        for (int ks = 0; ks < 32; ks += 8) {
            uint32_t af[2][4], bf[8][2];
#pragma unroll
            for (int mt = 0; mt < 2; mt++) {
                int m0 = wm * 32 + mt * 16 + gid;
                af[mt][0] = __float_as_uint(as[m0 * 36 + ks + tig]);
                af[mt][1] = __float_as_uint(as[(m0 + 8) * 36 + ks + tig]);
                af[mt][2] = __float_as_uint(as[m0 * 36 + ks + tig + 4]);
                af[mt][3] = __float_as_uint(as[(m0 + 8) * 36 + ks + tig + 4]);
            }
#pragma unroll
            for (int nt = 0; nt < 8; nt++) {
                int n0 = wn * 64 + nt * 8 + gid;
                bf[nt][0] = __float_as_uint(ws[n0 * 36 + ks + tig]);
                bf[nt][1] = __float_as_uint(ws[n0 * 36 + ks + tig + 4]);
            }
#pragma unroll
            for (int mt = 0; mt < 2; mt++)
#pragma unroll
                for (int nt = 0; nt < 8; nt++)
                    mma8(acc[mt][nt], af[mt], bf[nt]);
        }
        __syncthreads();
    }

    // epilogue
    const int brow = blockIdx.y * 128;
    const int bcol = blockIdx.x * 128;
#pragma unroll
    for (int mt = 0; mt < 2; mt++) {
#pragma unroll
        for (int nt = 0; nt < 8; nt++) {
            int r0  = brow + wm * 32 + mt * 16 + gid;
            int col = bcol + wn * 64 + nt * 8 + tig * 2;
            float v0 = acc[mt][nt][0], v1 = acc[mt][nt][1];
            float v2 = acc[mt][nt][2], v3 = acc[mt][nt][3];
            if (EPI == EPI_BIAS) {
                float b0 = bias[col], b1 = bias[col + 1];
                v0 += b0; v1 += b1; v2 += b0; v3 += b1;
            } else if (EPI == EPI_GELU) {
                float b0 = bias[col], b1 = bias[col + 1];
                v0 = gelu_tanh(v0 + b0); v1 = gelu_tanh(v1 + b1);
                v2 = gelu_tanh(v2 + b0); v3 = gelu_tanh(v3 + b1);
            }
            *reinterpret_cast<float2*>(C + (size_t)r0 * Ncols + col)       = make_float2(v0, v1);
            *reinterpret_cast<float2*>(C + (size_t)(r0 + 8) * Ncols + col) = make_float2(v2, v3);
        }
    }
}

// ---------------------------------------------------------------------------
// Flash attention (tf32 mma, online softmax).
// Grid (N/128, H, B), 256 threads = 8 warps; warp w owns q rows w*16..w*16+15.
// KV tiled by 64. q,k,v: [B,H,Nk,64]; mask: [B,N,Nk]; out: [B,N,H*64].
// smem (dynamic, 104,448 B): Qs[128][68], Ks[64][68], Vs[64][68], Ps[128][68].
// ---------------------------------------------------------------------------
#define FL_SMEM ((128 * 68 + 64 * 68 + 64 * 68 + 128 * 68) * 4)

__global__ void __launch_bounds__(256, 2)
flash_attn(const float* __restrict__ q, const float* __restrict__ k,
           const float* __restrict__ v, const float* __restrict__ mask,
           float* __restrict__ out, int Nk, long long mbstride) {
    extern __shared__ float sm[];
    float* Qs = sm;                    // [128][68]
    float* Ks = Qs + 128 * 68;         // [64][68]
    float* Vs = Ks + 64 * 68;          // [64][68]
    float* Ps = Vs + 64 * 68;          // [128][68]

    const int tid = threadIdx.x;
    const int w = tid >> 5, lane = tid & 31;
    const int gid = lane >> 2, tig = lane & 3;
    const int q0 = blockIdx.x * 128, h = blockIdx.y, b = blockIdx.z;

    const float* qb = q + ((size_t)(b * H_ + h) * N_ + q0) * 64;
    const float* kb = k + (size_t)(b * H_ + h) * Nk * 64;
    const float* vb = v + (size_t)(b * H_ + h) * Nk * 64;
    const float* mb = mask + (size_t)b * mbstride + (size_t)q0 * Nk;

    // load Q tile (persistent)
#pragma unroll
    for (int i = 0; i < 8; i++) {
        int flat = i * 256 + tid;
        int row = flat >> 4, c4 = (flat & 15) << 2;
        *reinterpret_cast<float4*>(&Qs[row * 68 + c4]) =
            *reinterpret_cast<const float4*>(qb + (size_t)row * 64 + c4);
    }

    const int r0 = w * 16 + gid, r1 = r0 + 8;   // local q rows of this thread
    float O[8][4];
#pragma unroll
    for (int nt = 0; nt < 8; nt++)
#pragma unroll
        for (int i = 0; i < 4; i++) O[nt][i] = 0.0f;
    float m0 = -3.0e38f, m1 = -3.0e38f, l0 = 0.0f, l1 = 0.0f;

    for (int kv0 = 0; kv0 < Nk; kv0 += 64) {
        // load K,V tiles
#pragma unroll
        for (int i = 0; i < 4; i++) {
            int flat = i * 256 + tid;
            int row = flat >> 4, c4 = (flat & 15) << 2;
            *reinterpret_cast<float4*>(&Ks[row * 68 + c4]) =
                *reinterpret_cast<const float4*>(kb + (size_t)(kv0 + row) * 64 + c4);
            *reinterpret_cast<float4*>(&Vs[row * 68 + c4]) =
                *reinterpret_cast<const float4*>(vb + (size_t)(kv0 + row) * 64 + c4);
        }
        __syncthreads();   // Ks/Vs ready (also guards Qs on first iter)

        // S = Q @ K^T (warp: 16 x 64)
        float sa[8][4];
#pragma unroll
        for (int nt = 0; nt < 8; nt++)
#pragma unroll
            for (int i = 0; i < 4; i++) sa[nt][i] = 0.0f;
#pragma unroll
        for (int ks = 0; ks < 64; ks += 8) {
            uint32_t af[4], bf[8][2];
            af[0] = __float_as_uint(Qs[r0 * 68 + ks + tig]);
            af[1] = __float_as_uint(Qs[r1 * 68 + ks + tig]);
            af[2] = __float_as_uint(Qs[r0 * 68 + ks + tig + 4]);
            af[3] = __float_as_uint(Qs[r1 * 68 + ks + tig + 4]);
#pragma unroll
            for (int nt = 0; nt < 8; nt++) {
                int n0 = nt * 8 + gid;
                bf[nt][0] = __float_as_uint(Ks[n0 * 68 + ks + tig]);
                bf[nt][1] = __float_as_uint(Ks[n0 * 68 + ks + tig + 4]);
            }
#pragma unroll
            for (int nt = 0; nt < 8; nt++) mma8(sa[nt], af, bf[nt]);
        }

        // scale + mask, tile row-max
        const float* mr0 = mb + (size_t)r0 * Nk + kv0;
        const float* mr1 = mb + (size_t)r1 * Nk + kv0;
        float tm0 = -3.0e38f, tm1 = -3.0e38f;
#pragma unroll
        for (int nt = 0; nt < 8; nt++) {
            int c = nt * 8 + tig * 2;
            float2 k0v = *reinterpret_cast<const float2*>(mr0 + c);
            float2 k1v = *reinterpret_cast<const float2*>(mr1 + c);
            sa[nt][0] = sa[nt][0] * 0.125f + k0v.x;
            sa[nt][1] = sa[nt][1] * 0.125f + k0v.y;
            sa[nt][2] = sa[nt][2] * 0.125f + k1v.x;
            sa[nt][3] = sa[nt][3] * 0.125f + k1v.y;
            tm0 = fmaxf(tm0, fmaxf(sa[nt][0], sa[nt][1]));
            tm1 = fmaxf(tm1, fmaxf(sa[nt][2], sa[nt][3]));
        }
        tm0 = fmaxf(tm0, __shfl_xor_sync(0xffffffffu, tm0, 1));
        tm0 = fmaxf(tm0, __shfl_xor_sync(0xffffffffu, tm0, 2));
        tm1 = fmaxf(tm1, __shfl_xor_sync(0xffffffffu, tm1, 1));
        tm1 = fmaxf(tm1, __shfl_xor_sync(0xffffffffu, tm1, 2));

        float mn0 = fmaxf(m0, tm0), mn1 = fmaxf(m1, tm1);
        float al0 = __expf(m0 - mn0), al1 = __expf(m1 - mn1);

        float ps0 = 0.0f, ps1 = 0.0f;
#pragma unroll
        for (int nt = 0; nt < 8; nt++) {
            float p0 = __expf(sa[nt][0] - mn0);
            float p1 = __expf(sa[nt][1] - mn0);
            float p2 = __expf(sa[nt][2] - mn1);
            float p3 = __expf(sa[nt][3] - mn1);
            ps0 += p0 + p1; ps1 += p2 + p3;
            int c = nt * 8 + tig * 2;
            *reinterpret_cast<float2*>(&Ps[r0 * 68 + c]) = make_float2(p0, p1);
            *reinterpret_cast<float2*>(&Ps[r1 * 68 + c]) = make_float2(p2, p3);
        }
        ps0 += __shfl_xor_sync(0xffffffffu, ps0, 1);
        ps0 += __shfl_xor_sync(0xffffffffu, ps0, 2);
        ps1 += __shfl_xor_sync(0xffffffffu, ps1, 1);
        ps1 += __shfl_xor_sync(0xffffffffu, ps1, 2);

        l0 = l0 * al0 + ps0; l1 = l1 * al1 + ps1;
        m0 = mn0; m1 = mn1;
#pragma unroll
        for (int nt = 0; nt < 8; nt++) {
            O[nt][0] *= al0; O[nt][1] *= al0;
            O[nt][2] *= al1; O[nt][3] *= al1;
        }
        __syncwarp();      // Ps rows are warp-private: warp-level visibility suffices

        // O += P @ V (warp: 16 x 64, k = 64)
#pragma unroll
        for (int ks = 0; ks < 64; ks += 8) {
            uint32_t af[4], bf[8][2];
            af[0] = __float_as_uint(Ps[r0 * 68 + ks + tig]);
            af[1] = __float_as_uint(Ps[r1 * 68 + ks + tig]);
            af[2] = __float_as_uint(Ps[r0 * 68 + ks + tig + 4]);
            af[3] = __float_as_uint(Ps[r1 * 68 + ks + tig + 4]);
#pragma unroll
            for (int nt = 0; nt < 8; nt++) {
                int n0 = nt * 8 + gid;
                bf[nt][0] = __float_as_uint(Vs[(ks + tig) * 68 + n0]);
                bf[nt][1] = __float_as_uint(Vs[(ks + tig + 4) * 68 + n0]);
            }
#pragma unroll
            for (int nt = 0; nt < 8; nt++) mma8(O[nt], af, bf[nt]);
        }
        __syncthreads();   // PV done before next tile overwrites Ks/Vs
    }

    // epilogue: normalize + write [B, N, H*64]
    const float iv0 = 1.0f / l0, iv1 = 1.0f / l1;
    float* o0 = out + ((size_t)b * N_ + q0 + r0) * 1024 + h * 64;
    float* o1 = out + ((size_t)b * N_ + q0 + r1) * 1024 + h * 64;
#pragma unroll
    for (int nt = 0; nt < 8; nt++) {
        int c = nt * 8 + tig * 2;
        *reinterpret_cast<float2*>(o0 + c) = make_float2(O[nt][0] * iv0, O[nt][1] * iv0);
        *reinterpret_cast<float2*>(o1 + c) = make_float2(O[nt][2] * iv1, O[nt][3] * iv1);
    }
}

// ---------------------------------------------------------------------------
// LayerNorm (+optional adaLN modulate). One block (256 thr) per row of D=1024.
// ---------------------------------------------------------------------------
__global__ void __launch_bounds__(256)
ln_mod_kernel(const float* __restrict__ x, const float* __restrict__ w,
              const float* __restrict__ sh, const float* __restrict__ sc,
              float* __restrict__ out) {
    __shared__ float rbuf[64];
    const int row = blockIdx.x;
    const int t = threadIdx.x;
    const float* xr = x + (size_t)row * D_;

    float vals[4];
    float sum = 0.f, sq = 0.f;
#pragma unroll
    for (int i = 0; i < 4; i++) {
        float v = xr[t + 256 * i];
        vals[i] = v; sum += v; sq += v * v;
    }
    for (int o = 16; o; o >>= 1) {
        sum += __shfl_xor_sync(0xffffffffu, sum, o);
        sq  += __shfl_xor_sync(0xffffffffu, sq, o);
    }
    if ((t & 31) == 0) { rbuf[t >> 5] = sum; rbuf[(t >> 5) + 32] = sq; }
    __syncthreads();
    if (t == 0) {
        float s = 0.f, qq = 0.f;
        for (int i = 0; i < 8; i++) { s += rbuf[i]; qq += rbuf[i + 32]; }
        float mean = s * (1.0f / D_);
        float var  = qq * (1.0f / D_) - mean * mean;
        rbuf[0] = mean; rbuf[1] = rsqrtf(var + 1e-5f);
    }
    __syncthreads();
    float mean = rbuf[0], inv = rbuf[1];

    const size_t mbase = (size_t)row * ADA_COLS;
    float* orow = out + (size_t)row * D_;
#pragma unroll
    for (int i = 0; i < 4; i++) {
        int col = t + 256 * i;
        float xn = (vals[i] - mean) * inv * w[col];
        if (sh != nullptr) xn = xn * (1.0f + sc[mbase + col]) + sh[mbase + col];
        orow[col] = xn;
    }
}

// ---------------------------------------------------------------------------
// Memory assembly + LayerNorm (rows pick h_content / h_obs)
// ---------------------------------------------------------------------------
__global__ void __launch_bounds__(256)
memln_kernel(const float* __restrict__ h_content, const float* __restrict__ h_obs,
             const float* __restrict__ w, float* __restrict__ out) {
    __shared__ float rbuf[64];
    const int row = blockIdx.x;            // 0..8191
    const int t = threadIdx.x;
    const int b = row >> 11;
    const int m = row & 2047;
    const float* xr = (m < N_)
        ? h_content + ((size_t)b * N_ + m) * D_
        : h_obs     + ((size_t)b * N_ + (m - N_)) * D_;

    float vals[4];
    float sum = 0.f, sq = 0.f;
#pragma unroll
    for (int i = 0; i < 4; i++) {
        float v = xr[t + 256 * i];
        vals[i] = v; sum += v; sq += v * v;
    }
    for (int o = 16; o; o >>= 1) {
        sum += __shfl_xor_sync(0xffffffffu, sum, o);
        sq  += __shfl_xor_sync(0xffffffffu, sq, o);
    }
    if ((t & 31) == 0) { rbuf[t >> 5] = sum; rbuf[(t >> 5) + 32] = sq; }
    __syncthreads();
    if (t == 0) {
        float s = 0.f, qq = 0.f;
        for (int i = 0; i < 8; i++) { s += rbuf[i]; qq += rbuf[i + 32]; }
        float mean = s * (1.0f / D_);
        float var  = qq * (1.0f / D_) - mean * mean;
        rbuf[0] = mean; rbuf[1] = rsqrtf(var + 1e-5f);
    }
    __syncthreads();
    float mean = rbuf[0], inv = rbuf[1];
    float* orow = out + (size_t)row * D_;
#pragma unroll
    for (int i = 0; i < 4; i++) {
        int col = t + 256 * i;
        orow[col] = (vals[i] - mean) * inv * w[col];
    }
}

// ---------------------------------------------------------------------------
// RoPE helpers. rotate_half partner = d^32, sign = (d<32) ? -1 : +1.
// ---------------------------------------------------------------------------
__global__ void rope_split_qkv(const float* __restrict__ qkv,
                               const float* __restrict__ cosb, const float* __restrict__ sinb,
                               float* __restrict__ q, float* __restrict__ k,
                               float* __restrict__ v) {
    int idx = blockIdx.x * blockDim.x + threadIdx.x;   // 4,194,304
    int d = idx & 63;
    int h = (idx >> 6) & 15;
    int n = (idx >> 10) & 1023;
    int b = idx >> 20;
    const float* row = qkv + (size_t)(b * N_ + n) * 3072;
    float c = cosb[n * 64 + d], s = sinb[n * 64 + d];
    int off = h * 64 + d;
    int poff = h * 64 + (d ^ 32);
    float sgn = (d < 32) ? -1.0f : 1.0f;
    float qv = row[off],        qp = row[poff];
    float kv = row[1024 + off], kp = row[1024 + poff];
    float vv = row[2048 + off];
    size_t o = (((size_t)(b * H_ + h)) * N_ + n) * 64 + d;
    q[o] = qv * c + sgn * qp * s;
    k[o] = kv * c + sgn * kp * s;
    v[o] = vv;
}

__global__ void rope_q_kernel(const float* __restrict__ qin,
                              const float* __restrict__ cosb, const float* __restrict__ sinb,
                              float* __restrict__ q) {
    int idx = blockIdx.x * blockDim.x + threadIdx.x;   // 4,194,304
    int d = idx & 63;
    int h = (idx >> 6) & 15;
    int n = (idx >> 10) & 1023;
    int b = idx >> 20;
    const float* row = qin + (size_t)(b * N_ + n) * D_;
    float c = cosb[n * 64 + d], s = sinb[n * 64 + d];
    float sgn = (d < 32) ? -1.0f : 1.0f;
    float x  = row[h * 64 + d];
    float xp = row[h * 64 + (d ^ 32)];
    q[(((size_t)(b * H_ + h)) * N_ + n) * 64 + d] = x * c + sgn * xp * s;
}

__global__ void rope_split_kv(const float* __restrict__ kv,
                              const float* __restrict__ cosb, const float* __restrict__ sinb,
                              float* __restrict__ k, float* __restrict__ v) {
    int idx = blockIdx.x * blockDim.x + threadIdx.x;   // 8,388,608
    int d = idx & 63;
    int h = (idx >> 6) & 15;
    int m = (idx >> 10) & 2047;
    int b = idx >> 21;
    const float* row = kv + (size_t)(b * M2_ + m) * 2048;
    int pos = m & 1023;
    float c = cosb[pos * 64 + d], s = sinb[pos * 64 + d];
    float sgn = (d < 32) ? -1.0f : 1.0f;
    float kx  = row[h * 64 + d];
    float kp  = row[h * 64 + (d ^ 32)];
    float vx  = row[1024 + h * 64 + d];
    size_t o = (((size_t)(b * H_ + h)) * M2_ + m) * 64 + d;
    k[o] = kx * c + sgn * kp * s;
    v[o] = vx;
}

// ---------------------------------------------------------------------------
// Residual + adaLN gate: out = xr + g * c
// ---------------------------------------------------------------------------
__global__ void resid_gate_kernel(const float* __restrict__ xr,
                                  const float* __restrict__ gbase,
                                  const float* __restrict__ c,
                                  float* __restrict__ out) {
    int idx = blockIdx.x * blockDim.x + threadIdx.x;  // 4,194,304
    int row = idx >> 10, col = idx & 1023;
    out[idx] = xr[idx] + gbase[(size_t)row * ADA_COLS + col] * c[idx];
}

// ---------------------------------------------------------------------------
// kernel_launch
// ---------------------------------------------------------------------------
extern "C" void kernel_launch(void* const* d_in, const int* in_sizes, int n_in,
                              void* d_out, int out_size) {
    (void)in_sizes; (void)n_in; (void)out_size;
    const float* q_x        = (const float*)d_in[0];
    const float* h_content  = (const float*)d_in[1];
    const float* h_obs      = (const float*)d_in[2];
    const float* t_cond     = (const float*)d_in[3];
    const float* cosb       = (const float*)d_in[4];
    const float* sinb       = (const float*)d_in[5];
    const float* M_QQ       = (const float*)d_in[6];
    const float* M_hyb      = (const float*)d_in[7];
    const float* w_ln_self  = (const float*)d_in[8];
    const float* w_qkv      = (const float*)d_in[9];
    const float* w_self_out = (const float*)d_in[10];
    const float* w_ln_cross = (const float*)d_in[11];
    const float* w_ln_mem   = (const float*)d_in[12];
    const float* w_qproj    = (const float*)d_in[13];
    const float* w_kvproj   = (const float*)d_in[14];
    const float* w_cross_out= (const float*)d_in[15];
    const float* w_ln_mlp   = (const float*)d_in[16];
    const float* w_mlp1     = (const float*)d_in[17];
    const float* b_mlp1     = (const float*)d_in[18];
    const float* w_mlp2     = (const float*)d_in[19];
    const float* b_mlp2     = (const float*)d_in[20];
    const float* w_ada      = (const float*)d_in[21];
    const float* b_ada      = (const float*)d_in[22];
    float* out = (float*)d_out;

    // Allow >48KB dynamic smem. Unconditional every call (no static guards —
    // harness contract). Idempotent, immediate (not a stream op): capture-safe.
    cudaFuncSetAttribute(mm_tf32<EPI_NONE>, cudaFuncAttributeMaxDynamicSharedMemorySize, MM_SMEM);
    cudaFuncSetAttribute(mm_tf32<EPI_BIAS>, cudaFuncAttributeMaxDynamicSharedMemorySize, MM_SMEM);
    cudaFuncSetAttribute(mm_tf32<EPI_GELU>, cudaFuncAttributeMaxDynamicSharedMemorySize, MM_SMEM);
    cudaFuncSetAttribute(flash_attn,        cudaFuncAttributeMaxDynamicSharedMemorySize, FL_SMEM);

    float* S = nullptr;
    cudaGetSymbolAddress((void**)&S, g_buf);
    float* ADA   = S + OFF_ADA;
    float* XN    = S + OFF_XN;
    float* QKV   = S + OFF_QKV;
    float* Q     = S + OFF_Q;
    float* K     = S + OFF_K;
    float* V     = S + OFF_V;
    float* ATTN  = S + OFF_ATTN;
    float* PROJ  = S + OFF_PROJ;
    float* X     = S + OFF_X;
    float* MEMLN = S + OFF_MEMLN;
    float* KV    = S + OFF_KV;
    float* QC    = S + OFF_QC;
    float* KC    = S + OFF_KC;
    float* VC    = S + OFF_VC;
    float* HBUF  = S + OFF_H;

    // ada = t_cond @ w_ada[:9216].T + b_ada
    mm_tf32<EPI_BIAS><<<dim3(72, 32), 256, MM_SMEM>>>(t_cond, w_ada, b_ada, ADA, COND_, ADA_COLS);

    // ---- Pass 1: self-attention ----
    ln_mod_kernel<<<BN_, 256>>>(q_x, w_ln_self, ADA + 0 * D_, ADA + 1 * D_, XN);
    mm_tf32<EPI_NONE><<<dim3(24, 32), 256, MM_SMEM>>>(XN, w_qkv, nullptr, QKV, D_, 3072);
    rope_split_qkv<<<4194304 / 256, 256>>>(QKV, cosb, sinb, Q, K, V);
    flash_attn<<<dim3(8, H_, B_), 256, FL_SMEM>>>(Q, K, V, M_QQ, ATTN, N_, (long long)N_ * N_);
    mm_tf32<EPI_NONE><<<dim3(8, 32), 256, MM_SMEM>>>(ATTN, w_self_out, nullptr, PROJ, D_, D_);
    resid_gate_kernel<<<4194304 / 256, 256>>>(q_x, ADA + 2 * D_, PROJ, X);

    // ---- Pass 2: cross-attention ----
    ln_mod_kernel<<<BN_, 256>>>(X, w_ln_cross, ADA + 3 * D_, ADA + 4 * D_, XN);
    mm_tf32<EPI_NONE><<<dim3(8, 32), 256, MM_SMEM>>>(XN, w_qproj, nullptr, QKV, D_, D_);
    rope_q_kernel<<<4194304 / 256, 256>>>(QKV, cosb, sinb, QC);
    memln_kernel<<<B_ * M2_, 256>>>(h_content, h_obs, w_ln_mem, MEMLN);
    mm_tf32<EPI_NONE><<<dim3(16, 64), 256, MM_SMEM>>>(MEMLN, w_kvproj, nullptr, KV, D_, 2048);
    rope_split_kv<<<8388608 / 256, 256>>>(KV, cosb, sinb, KC, VC);
    flash_attn<<<dim3(8, H_, B_), 256, FL_SMEM>>>(QC, KC, VC, M_hyb, ATTN, M2_, (long long)N_ * M2_);
    mm_tf32<EPI_NONE><<<dim3(8, 32), 256, MM_SMEM>>>(ATTN, w_cross_out, nullptr, PROJ, D_, D_);
    resid_gate_kernel<<<4194304 / 256, 256>>>(X, ADA + 5 * D_, PROJ, X);

    // ---- Pass 3: MLP ----
    ln_mod_kernel<<<BN_, 256>>>(X, w_ln_mlp, ADA + 6 * D_, ADA + 7 * D_, XN);
    mm_tf32<EPI_GELU><<<dim3(32, 32), 256, MM_SMEM>>>(XN, w_mlp1, b_mlp1, HBUF, D_, 4096);
    mm_tf32<EPI_BIAS><<<dim3(8, 32), 256, MM_SMEM>>>(HBUF, w_mlp2, b_mlp2, PROJ, 4096, D_);
    resid_gate_kernel<<<4194304 / 256, 256>>>(X, ADA + 8 * D_, PROJ, out);
}

// round 6
// speedup vs baseline: 8.3742x; 1.0027x over previous
#include <cuda_runtime.h>
#include <math.h>
#include <stdint.h>

// ---------------------------------------------------------------------------
// Problem constants
// ---------------------------------------------------------------------------
#define B_   4
#define N_   1024
#define D_   1024
#define H_   16
#define COND_ 256
#define BN_  (B_ * N_)        // 4096 rows
#define M2_  (2 * N_)         // 2048 memory tokens
#define ADA_COLS 9216         // first 9 of 12 D-chunks of ada

// ---------------------------------------------------------------------------
// Scratch (single static device buffer; no allocations anywhere)
// ---------------------------------------------------------------------------
static const size_t OFF_ADA   = 0;                          // [4096, 9216]
static const size_t OFF_XN    = OFF_ADA   + 37748736UL;     // [4096, 1024]
static const size_t OFF_QKV   = OFF_XN    + 4194304UL;      // [4096, 3072]
static const size_t OFF_Q     = OFF_QKV   + 12582912UL;     // [B,H,N,64]
static const size_t OFF_K     = OFF_Q     + 4194304UL;
static const size_t OFF_V     = OFF_K     + 4194304UL;
static const size_t OFF_ATTN  = OFF_V     + 4194304UL;      // [4096, 1024]
static const size_t OFF_PROJ  = OFF_ATTN  + 4194304UL;      // [4096, 1024]
static const size_t OFF_X     = OFF_PROJ  + 4194304UL;      // residual stream
static const size_t OFF_MEMLN = OFF_X     + 4194304UL;      // [8192, 1024]
static const size_t OFF_KV    = OFF_MEMLN + 8388608UL;      // [8192, 2048]
static const size_t OFF_QC    = OFF_KV    + 16777216UL;     // [B,H,N,64]
static const size_t OFF_KC    = OFF_QC    + 4194304UL;      // [B,H,2N,64]
static const size_t OFF_VC    = OFF_KC    + 8388608UL;      // [B,H,2N,64]
static const size_t OFF_H     = OFF_VC    + 8388608UL;      // [4096,4096] MLP hidden
static const size_t SCRATCH_TOTAL = OFF_H + 16777216UL;

__device__ float g_buf[SCRATCH_TOTAL];

// ---------------------------------------------------------------------------
// Helpers
// ---------------------------------------------------------------------------
__device__ __forceinline__ float gelu_tanh(float x) {
    float x3 = x * x * x;
    return 0.5f * x * (1.0f + tanhf(0.7978845608028654f * (x + 0.044715f * x3)));
}

// tf32 mma, fp32 accumulate. Raw fp32 in registers: HW reads top 19 bits
// (RZ truncation) — acceptable vs 1e-3 budget.
__device__ __forceinline__ void mma8(float c[4], const uint32_t a[4], const uint32_t b[2]) {
    asm volatile(
        "mma.sync.aligned.m16n8k8.row.col.f32.tf32.tf32.f32 "
        "{%0,%1,%2,%3}, {%4,%5,%6,%7}, {%8,%9}, {%0,%1,%2,%3};\n"
        : "+f"(c[0]), "+f"(c[1]), "+f"(c[2]), "+f"(c[3])
        : "r"(a[0]), "r"(a[1]), "r"(a[2]), "r"(a[3]), "r"(b[0]), "r"(b[1]));
}

__device__ __forceinline__ void cp16(uint32_t saddr, const void* gptr) {
    asm volatile("cp.async.ca.shared.global [%0], [%1], 16;\n" :: "r"(saddr), "l"(gptr));
}

// ---------------------------------------------------------------------------
// TF32 GEMM: C[M,Ncols] = A[M,K] @ W[Ncols,K]^T, 3-stage cp.async pipeline.
// 128x128x32 tile, 256 threads (4x2 warps), warp tile 32x64.
// smem: 2 * 3 * 128 * 36 floats = 110,592 B (dynamic).
// ---------------------------------------------------------------------------
#define EPI_NONE 0
#define EPI_BIAS 1
#define EPI_GELU 2
#define MM_SMEM (2 * 3 * 128 * 36 * 4)

template<int EPI>
__global__ void __launch_bounds__(256, 2)
mm_tf32(const float* __restrict__ A, const float* __restrict__ W,
        const float* __restrict__ bias, float* __restrict__ C,
        int K, int Ncols) {
    extern __shared__ float sm[];
    float* AsB = sm;                 // [3][128][36]
    float* WsB = sm + 3 * 128 * 36;

    const int tid  = threadIdx.x;
    const int wid  = tid >> 5, lane = tid & 31;
    const int wm   = wid >> 1, wn   = wid & 1;
    const int gid  = lane >> 2, tig = lane & 3;
    const int lrow = tid >> 3;          // 0..31
    const int lcol = (tid & 7) << 2;    // 0,4,..,28

    const float* Ab = A + (size_t)blockIdx.y * 128 * K;
    const float* Wb = W + (size_t)blockIdx.x * 128 * K;

    const uint32_t asb = (uint32_t)__cvta_generic_to_shared(AsB);
    const uint32_t wsb = (uint32_t)__cvta_generic_to_shared(WsB);

    auto issue = [&](int st, int kt) {
        const int k0 = kt * 32;
        const uint32_t sst = (uint32_t)(st * 128 * 36) * 4;
#pragma unroll
        for (int i = 0; i < 4; i++) {
            int r = lrow + i * 32;
            uint32_t so = sst + (uint32_t)(r * 36 + lcol) * 4;
            cp16(asb + so, Ab + (size_t)r * K + k0 + lcol);
            cp16(wsb + so, Wb + (size_t)r * K + k0 + lcol);
        }
        asm volatile("cp.async.commit_group;\n");
    };

    float acc[2][8][4];
#pragma unroll
    for (int mt = 0; mt < 2; mt++)
#pragma unroll
        for (int nt = 0; nt < 8; nt++)
#pragma unroll
            for (int i = 0; i < 4; i++) acc[mt][nt][i] = 0.0f;

    const int nkt = K / 32;
    issue(0, 0);
    issue(1, 1);

    for (int kt = 0; kt < nkt; kt++) {
        asm volatile("cp.async.wait_group 1;\n");
        __syncthreads();
        const int nk = kt + 2;
        if (nk < nkt) issue(nk % 3, nk);

        const float* as = AsB + (kt % 3) * 128 * 36;
        const float* ws = WsB + (kt % 3) * 128 * 36;
#pragma unroll
        for (int ks = 0; ks < 32; ks += 8) {
            uint32_t af[2][4], bf[8][2];
#pragma unroll
            for (int mt = 0; mt < 2; mt++) {
                int m0 = wm * 32 + mt * 16 + gid;
                af[mt][0] = __float_as_uint(as[m0 * 36 + ks + tig]);
                af[mt][1] = __float_as_uint(as[(m0 + 8) * 36 + ks + tig]);
                af[mt][2] = __float_as_uint(as[m0 * 36 + ks + tig + 4]);
                af[mt][3] = __float_as_uint(as[(m0 + 8) * 36 + ks + tig + 4]);
            }
#pragma unroll
            for (int nt = 0; nt < 8; nt++) {
                int n0 = wn * 64 + nt * 8 + gid;
                bf[nt][0] = __float_as_uint(ws[n0 * 36 + ks + tig]);
                bf[nt][1] = __float_as_uint(ws[n0 * 36 + ks + tig + 4]);
            }
#pragma unroll
            for (int mt = 0; mt < 2; mt++)
#pragma unroll
                for (int nt = 0; nt < 8; nt++)
                    mma8(acc[mt][nt], af[mt], bf[nt]);
        }
        __syncthreads();
    }

    // epilogue
    const int brow = blockIdx.y * 128;
    const int bcol = blockIdx.x * 128;
#pragma unroll
    for (int mt = 0; mt < 2; mt++) {
#pragma unroll
        for (int nt = 0; nt < 8; nt++) {
            int r0  = brow + wm * 32 + mt * 16 + gid;
            int col = bcol + wn * 64 + nt * 8 + tig * 2;
            float v0 = acc[mt][nt][0], v1 = acc[mt][nt][1];
            float v2 = acc[mt][nt][2], v3 = acc[mt][nt][3];
            if (EPI == EPI_BIAS) {
                float b0 = bias[col], b1 = bias[col + 1];
                v0 += b0; v1 += b1; v2 += b0; v3 += b1;
            } else if (EPI == EPI_GELU) {
                float b0 = bias[col], b1 = bias[col + 1];
                v0 = gelu_tanh(v0 + b0); v1 = gelu_tanh(v1 + b1);
                v2 = gelu_tanh(v2 + b0); v3 = gelu_tanh(v3 + b1);
            }
            *reinterpret_cast<float2*>(C + (size_t)r0 * Ncols + col)       = make_float2(v0, v1);
            *reinterpret_cast<float2*>(C + (size_t)(r0 + 8) * Ncols + col) = make_float2(v2, v3);
        }
    }
}

// ---------------------------------------------------------------------------
// Flash attention (tf32 mma, online softmax).
// Grid (N/128, H, B), 256 threads = 8 warps; warp w owns q rows w*16..w*16+15.
// KV tiled by 64. q,k,v: [B,H,Nk,64]; mask: [B,N,Nk]; out: [B,N,H*64].
// smem (dynamic, 104,448 B): Qs[128][68], Ks[64][68], Vs[64][68], Ps[128][68].
// ---------------------------------------------------------------------------
#define FL_SMEM ((128 * 68 + 64 * 68 + 64 * 68 + 128 * 68) * 4)

__global__ void __launch_bounds__(256, 2)
flash_attn(const float* __restrict__ q, const float* __restrict__ k,
           const float* __restrict__ v, const float* __restrict__ mask,
           float* __restrict__ out, int Nk, long long mbstride) {
    extern __shared__ float sm[];
    float* Qs = sm;                    // [128][68]
    float* Ks = Qs + 128 * 68;         // [64][68]
    float* Vs = Ks + 64 * 68;          // [64][68]
    float* Ps = Vs + 64 * 68;          // [128][68]

    const int tid = threadIdx.x;
    const int w = tid >> 5, lane = tid & 31;
    const int gid = lane >> 2, tig = lane & 3;
    const int q0 = blockIdx.x * 128, h = blockIdx.y, b = blockIdx.z;

    const float* qb = q + ((size_t)(b * H_ + h) * N_ + q0) * 64;
    const float* kb = k + (size_t)(b * H_ + h) * Nk * 64;
    const float* vb = v + (size_t)(b * H_ + h) * Nk * 64;
    const float* mb = mask + (size_t)b * mbstride + (size_t)q0 * Nk;

    // load Q tile (persistent)
#pragma unroll
    for (int i = 0; i < 8; i++) {
        int flat = i * 256 + tid;
        int row = flat >> 4, c4 = (flat & 15) << 2;
        *reinterpret_cast<float4*>(&Qs[row * 68 + c4]) =
            *reinterpret_cast<const float4*>(qb + (size_t)row * 64 + c4);
    }

    const int r0 = w * 16 + gid, r1 = r0 + 8;   // local q rows of this thread
    float O[8][4];
#pragma unroll
    for (int nt = 0; nt < 8; nt++)
#pragma unroll
        for (int i = 0; i < 4; i++) O[nt][i] = 0.0f;
    float m0 = -3.0e38f, m1 = -3.0e38f, l0 = 0.0f, l1 = 0.0f;

    for (int kv0 = 0; kv0 < Nk; kv0 += 64) {
        // load K,V tiles
#pragma unroll
        for (int i = 0; i < 4; i++) {
            int flat = i * 256 + tid;
            int row = flat >> 4, c4 = (flat & 15) << 2;
            *reinterpret_cast<float4*>(&Ks[row * 68 + c4]) =
                *reinterpret_cast<const float4*>(kb + (size_t)(kv0 + row) * 64 + c4);
            *reinterpret_cast<float4*>(&Vs[row * 68 + c4]) =
                *reinterpret_cast<const float4*>(vb + (size_t)(kv0 + row) * 64 + c4);
        }
        __syncthreads();   // Ks/Vs ready (also guards Qs on first iter)

        // S = Q @ K^T (warp: 16 x 64)
        float sa[8][4];
#pragma unroll
        for (int nt = 0; nt < 8; nt++)
#pragma unroll
            for (int i = 0; i < 4; i++) sa[nt][i] = 0.0f;
#pragma unroll
        for (int ks = 0; ks < 64; ks += 8) {
            uint32_t af[4], bf[8][2];
            af[0] = __float_as_uint(Qs[r0 * 68 + ks + tig]);
            af[1] = __float_as_uint(Qs[r1 * 68 + ks + tig]);
            af[2] = __float_as_uint(Qs[r0 * 68 + ks + tig + 4]);
            af[3] = __float_as_uint(Qs[r1 * 68 + ks + tig + 4]);
#pragma unroll
            for (int nt = 0; nt < 8; nt++) {
                int n0 = nt * 8 + gid;
                bf[nt][0] = __float_as_uint(Ks[n0 * 68 + ks + tig]);
                bf[nt][1] = __float_as_uint(Ks[n0 * 68 + ks + tig + 4]);
            }
#pragma unroll
            for (int nt = 0; nt < 8; nt++) mma8(sa[nt], af, bf[nt]);
        }

        // scale + mask, tile row-max
        const float* mr0 = mb + (size_t)r0 * Nk + kv0;
        const float* mr1 = mb + (size_t)r1 * Nk + kv0;
        float tm0 = -3.0e38f, tm1 = -3.0e38f;
#pragma unroll
        for (int nt = 0; nt < 8; nt++) {
            int c = nt * 8 + tig * 2;
            float2 k0v = *reinterpret_cast<const float2*>(mr0 + c);
            float2 k1v = *reinterpret_cast<const float2*>(mr1 + c);
            sa[nt][0] = sa[nt][0] * 0.125f + k0v.x;
            sa[nt][1] = sa[nt][1] * 0.125f + k0v.y;
            sa[nt][2] = sa[nt][2] * 0.125f + k1v.x;
            sa[nt][3] = sa[nt][3] * 0.125f + k1v.y;
            tm0 = fmaxf(tm0, fmaxf(sa[nt][0], sa[nt][1]));
            tm1 = fmaxf(tm1, fmaxf(sa[nt][2], sa[nt][3]));
        }
        tm0 = fmaxf(tm0, __shfl_xor_sync(0xffffffffu, tm0, 1));
        tm0 = fmaxf(tm0, __shfl_xor_sync(0xffffffffu, tm0, 2));
        tm1 = fmaxf(tm1, __shfl_xor_sync(0xffffffffu, tm1, 1));
        tm1 = fmaxf(tm1, __shfl_xor_sync(0xffffffffu, tm1, 2));

        float mn0 = fmaxf(m0, tm0), mn1 = fmaxf(m1, tm1);
        float al0 = __expf(m0 - mn0), al1 = __expf(m1 - mn1);

        float ps0 = 0.0f, ps1 = 0.0f;
#pragma unroll
        for (int nt = 0; nt < 8; nt++) {
            float p0 = __expf(sa[nt][0] - mn0);
            float p1 = __expf(sa[nt][1] - mn0);
            float p2 = __expf(sa[nt][2] - mn1);
            float p3 = __expf(sa[nt][3] - mn1);
            ps0 += p0 + p1; ps1 += p2 + p3;
            int c = nt * 8 + tig * 2;
            *reinterpret_cast<float2*>(&Ps[r0 * 68 + c]) = make_float2(p0, p1);
            *reinterpret_cast<float2*>(&Ps[r1 * 68 + c]) = make_float2(p2, p3);
        }
        ps0 += __shfl_xor_sync(0xffffffffu, ps0, 1);
        ps0 += __shfl_xor_sync(0xffffffffu, ps0, 2);
        ps1 += __shfl_xor_sync(0xffffffffu, ps1, 1);
        ps1 += __shfl_xor_sync(0xffffffffu, ps1, 2);

        l0 = l0 * al0 + ps0; l1 = l1 * al1 + ps1;
        m0 = mn0; m1 = mn1;
#pragma unroll
        for (int nt = 0; nt < 8; nt++) {
            O[nt][0] *= al0; O[nt][1] *= al0;
            O[nt][2] *= al1; O[nt][3] *= al1;
        }
        __syncwarp();      // Ps rows are warp-private: warp-level visibility suffices

        // O += P @ V (warp: 16 x 64, k = 64)
#pragma unroll
        for (int ks = 0; ks < 64; ks += 8) {
            uint32_t af[4], bf[8][2];
            af[0] = __float_as_uint(Ps[r0 * 68 + ks + tig]);
            af[1] = __float_as_uint(Ps[r1 * 68 + ks + tig]);
            af[2] = __float_as_uint(Ps[r0 * 68 + ks + tig + 4]);
            af[3] = __float_as_uint(Ps[r1 * 68 + ks + tig + 4]);
#pragma unroll
            for (int nt = 0; nt < 8; nt++) {
                int n0 = nt * 8 + gid;
                bf[nt][0] = __float_as_uint(Vs[(ks + tig) * 68 + n0]);
                bf[nt][1] = __float_as_uint(Vs[(ks + tig + 4) * 68 + n0]);
            }
#pragma unroll
            for (int nt = 0; nt < 8; nt++) mma8(O[nt], af, bf[nt]);
        }
        __syncthreads();   // PV done before next tile overwrites Ks/Vs
    }

    // epilogue: normalize + write [B, N, H*64]
    const float iv0 = 1.0f / l0, iv1 = 1.0f / l1;
    float* o0 = out + ((size_t)b * N_ + q0 + r0) * 1024 + h * 64;
    float* o1 = out + ((size_t)b * N_ + q0 + r1) * 1024 + h * 64;
#pragma unroll
    for (int nt = 0; nt < 8; nt++) {
        int c = nt * 8 + tig * 2;
        *reinterpret_cast<float2*>(o0 + c) = make_float2(O[nt][0] * iv0, O[nt][1] * iv0);
        *reinterpret_cast<float2*>(o1 + c) = make_float2(O[nt][2] * iv1, O[nt][3] * iv1);
    }
}

// ---------------------------------------------------------------------------
// LayerNorm (+optional adaLN modulate). One block (256 thr) per row of D=1024.
// ---------------------------------------------------------------------------
__global__ void __launch_bounds__(256)
ln_mod_kernel(const float* __restrict__ x, const float* __restrict__ w,
              const float* __restrict__ sh, const float* __restrict__ sc,
              float* __restrict__ out) {
    __shared__ float rbuf[64];
    const int row = blockIdx.x;
    const int t = threadIdx.x;
    const float* xr = x + (size_t)row * D_;

    float vals[4];
    float sum = 0.f, sq = 0.f;
#pragma unroll
    for (int i = 0; i < 4; i++) {
        float v = xr[t + 256 * i];
        vals[i] = v; sum += v; sq += v * v;
    }
    for (int o = 16; o; o >>= 1) {
        sum += __shfl_xor_sync(0xffffffffu, sum, o);
        sq  += __shfl_xor_sync(0xffffffffu, sq, o);
    }
    if ((t & 31) == 0) { rbuf[t >> 5] = sum; rbuf[(t >> 5) + 32] = sq; }
    __syncthreads();
    if (t == 0) {
        float s = 0.f, qq = 0.f;
        for (int i = 0; i < 8; i++) { s += rbuf[i]; qq += rbuf[i + 32]; }
        float mean = s * (1.0f / D_);
        float var  = qq * (1.0f / D_) - mean * mean;
        rbuf[0] = mean; rbuf[1] = rsqrtf(var + 1e-5f);
    }
    __syncthreads();
    float mean = rbuf[0], inv = rbuf[1];

    const size_t mbase = (size_t)row * ADA_COLS;
    float* orow = out + (size_t)row * D_;
#pragma unroll
    for (int i = 0; i < 4; i++) {
        int col = t + 256 * i;
        float xn = (vals[i] - mean) * inv * w[col];
        if (sh != nullptr) xn = xn * (1.0f + sc[mbase + col]) + sh[mbase + col];
        orow[col] = xn;
    }
}

// ---------------------------------------------------------------------------
// Memory assembly + LayerNorm (rows pick h_content / h_obs)
// ---------------------------------------------------------------------------
__global__ void __launch_bounds__(256)
memln_kernel(const float* __restrict__ h_content, const float* __restrict__ h_obs,
             const float* __restrict__ w, float* __restrict__ out) {
    __shared__ float rbuf[64];
    const int row = blockIdx.x;            // 0..8191
    const int t = threadIdx.x;
    const int b = row >> 11;
    const int m = row & 2047;
    const float* xr = (m < N_)
        ? h_content + ((size_t)b * N_ + m) * D_
        : h_obs     + ((size_t)b * N_ + (m - N_)) * D_;

    float vals[4];
    float sum = 0.f, sq = 0.f;
#pragma unroll
    for (int i = 0; i < 4; i++) {
        float v = xr[t + 256 * i];
        vals[i] = v; sum += v; sq += v * v;
    }
    for (int o = 16; o; o >>= 1) {
        sum += __shfl_xor_sync(0xffffffffu, sum, o);
        sq  += __shfl_xor_sync(0xffffffffu, sq, o);
    }
    if ((t & 31) == 0) { rbuf[t >> 5] = sum; rbuf[(t >> 5) + 32] = sq; }
    __syncthreads();
    if (t == 0) {
        float s = 0.f, qq = 0.f;
        for (int i = 0; i < 8; i++) { s += rbuf[i]; qq += rbuf[i + 32]; }
        float mean = s * (1.0f / D_);
        float var  = qq * (1.0f / D_) - mean * mean;
        rbuf[0] = mean; rbuf[1] = rsqrtf(var + 1e-5f);
    }
    __syncthreads();
    float mean = rbuf[0], inv = rbuf[1];
    float* orow = out + (size_t)row * D_;
#pragma unroll
    for (int i = 0; i < 4; i++) {
        int col = t + 256 * i;
        orow[col] = (vals[i] - mean) * inv * w[col];
    }
}

// ---------------------------------------------------------------------------
// RoPE helpers. rotate_half partner = d^32, sign = (d<32) ? -1 : +1.
// ---------------------------------------------------------------------------
__global__ void rope_split_qkv(const float* __restrict__ qkv,
                               const float* __restrict__ cosb, const float* __restrict__ sinb,
                               float* __restrict__ q, float* __restrict__ k,
                               float* __restrict__ v) {
    int idx = blockIdx.x * blockDim.x + threadIdx.x;   // 4,194,304
    int d = idx & 63;
    int h = (idx >> 6) & 15;
    int n = (idx >> 10) & 1023;
    int b = idx >> 20;
    const float* row = qkv + (size_t)(b * N_ + n) * 3072;
    float c = cosb[n * 64 + d], s = sinb[n * 64 + d];
    int off = h * 64 + d;
    int poff = h * 64 + (d ^ 32);
    float sgn = (d < 32) ? -1.0f : 1.0f;
    float qv = row[off],        qp = row[poff];
    float kv = row[1024 + off], kp = row[1024 + poff];
    float vv = row[2048 + off];
    size_t o = (((size_t)(b * H_ + h)) * N_ + n) * 64 + d;
    q[o] = qv * c + sgn * qp * s;
    k[o] = kv * c + sgn * kp * s;
    v[o] = vv;
}

__global__ void rope_q_kernel(const float* __restrict__ qin,
                              const float* __restrict__ cosb, const float* __restrict__ sinb,
                              float* __restrict__ q) {
    int idx = blockIdx.x * blockDim.x + threadIdx.x;   // 4,194,304
    int d = idx & 63;
    int h = (idx >> 6) & 15;
    int n = (idx >> 10) & 1023;
    int b = idx >> 20;
    const float* row = qin + (size_t)(b * N_ + n) * D_;
    float c = cosb[n * 64 + d], s = sinb[n * 64 + d];
    float sgn = (d < 32) ? -1.0f : 1.0f;
    float x  = row[h * 64 + d];
    float xp = row[h * 64 + (d ^ 32)];
    q[(((size_t)(b * H_ + h)) * N_ + n) * 64 + d] = x * c + sgn * xp * s;
}

__global__ void rope_split_kv(const float* __restrict__ kv,
                              const float* __restrict__ cosb, const float* __restrict__ sinb,
                              float* __restrict__ k, float* __restrict__ v) {
    int idx = blockIdx.x * blockDim.x + threadIdx.x;   // 8,388,608
    int d = idx & 63;
    int h = (idx >> 6) & 15;
    int m = (idx >> 10) & 2047;
    int b = idx >> 21;
    const float* row = kv + (size_t)(b * M2_ + m) * 2048;
    int pos = m & 1023;
    float c = cosb[pos * 64 + d], s = sinb[pos * 64 + d];
    float sgn = (d < 32) ? -1.0f : 1.0f;
    float kx  = row[h * 64 + d];
    float kp  = row[h * 64 + (d ^ 32)];
    float vx  = row[1024 + h * 64 + d];
    size_t o = (((size_t)(b * H_ + h)) * M2_ + m) * 64 + d;
    k[o] = kx * c + sgn * kp * s;
    v[o] = vx;
}

// ---------------------------------------------------------------------------
// Residual + adaLN gate: out = xr + g * c
// ---------------------------------------------------------------------------
__global__ void resid_gate_kernel(const float* __restrict__ xr,
                                  const float* __restrict__ gbase,
                                  const float* __restrict__ c,
                                  float* __restrict__ out) {
    int idx = blockIdx.x * blockDim.x + threadIdx.x;  // 4,194,304
    int row = idx >> 10, col = idx & 1023;
    out[idx] = xr[idx] + gbase[(size_t)row * ADA_COLS + col] * c[idx];
}

// ---------------------------------------------------------------------------
// kernel_launch
// ---------------------------------------------------------------------------
extern "C" void kernel_launch(void* const* d_in, const int* in_sizes, int n_in,
                              void* d_out, int out_size) {
    (void)in_sizes; (void)n_in; (void)out_size;
    const float* q_x        = (const float*)d_in[0];
    const float* h_content  = (const float*)d_in[1];
    const float* h_obs      = (const float*)d_in[2];
    const float* t_cond     = (const float*)d_in[3];
    const float* cosb       = (const float*)d_in[4];
    const float* sinb       = (const float*)d_in[5];
    const float* M_QQ       = (const float*)d_in[6];
    const float* M_hyb      = (const float*)d_in[7];
    const float* w_ln_self  = (const float*)d_in[8];
    const float* w_qkv      = (const float*)d_in[9];
    const float* w_self_out = (const float*)d_in[10];
    const float* w_ln_cross = (const float*)d_in[11];
    const float* w_ln_mem   = (const float*)d_in[12];
    const float* w_qproj    = (const float*)d_in[13];
    const float* w_kvproj   = (const float*)d_in[14];
    const float* w_cross_out= (const float*)d_in[15];
    const float* w_ln_mlp   = (const float*)d_in[16];
    const float* w_mlp1     = (const float*)d_in[17];
    const float* b_mlp1     = (const float*)d_in[18];
    const float* w_mlp2     = (const float*)d_in[19];
    const float* b_mlp2     = (const float*)d_in[20];
    const float* w_ada      = (const float*)d_in[21];
    const float* b_ada      = (const float*)d_in[22];
    float* out = (float*)d_out;

    // Allow >48KB dynamic smem. Unconditional every call (no static guards —
    // harness contract). Idempotent, immediate (not a stream op): capture-safe.
    cudaFuncSetAttribute(mm_tf32<EPI_NONE>, cudaFuncAttributeMaxDynamicSharedMemorySize, MM_SMEM);
    cudaFuncSetAttribute(mm_tf32<EPI_BIAS>, cudaFuncAttributeMaxDynamicSharedMemorySize, MM_SMEM);
    cudaFuncSetAttribute(mm_tf32<EPI_GELU>, cudaFuncAttributeMaxDynamicSharedMemorySize, MM_SMEM);
    cudaFuncSetAttribute(flash_attn,        cudaFuncAttributeMaxDynamicSharedMemorySize, FL_SMEM);

    float* S = nullptr;
    cudaGetSymbolAddress((void**)&S, g_buf);
    float* ADA   = S + OFF_ADA;
    float* XN    = S + OFF_XN;
    float* QKV   = S + OFF_QKV;
    float* Q     = S + OFF_Q;
    float* K     = S + OFF_K;
    float* V     = S + OFF_V;
    float* ATTN  = S + OFF_ATTN;
    float* PROJ  = S + OFF_PROJ;
    float* X     = S + OFF_X;
    float* MEMLN = S + OFF_MEMLN;
    float* KV    = S + OFF_KV;
    float* QC    = S + OFF_QC;
    float* KC    = S + OFF_KC;
    float* VC    = S + OFF_VC;
    float* HBUF  = S + OFF_H;

    // ada = t_cond @ w_ada[:9216].T + b_ada
    mm_tf32<EPI_BIAS><<<dim3(72, 32), 256, MM_SMEM>>>(t_cond, w_ada, b_ada, ADA, COND_, ADA_COLS);

    // ---- Pass 1: self-attention ----
    ln_mod_kernel<<<BN_, 256>>>(q_x, w_ln_self, ADA + 0 * D_, ADA + 1 * D_, XN);
    mm_tf32<EPI_NONE><<<dim3(24, 32), 256, MM_SMEM>>>(XN, w_qkv, nullptr, QKV, D_, 3072);
    rope_split_qkv<<<4194304 / 256, 256>>>(QKV, cosb, sinb, Q, K, V);
    flash_attn<<<dim3(8, H_, B_), 256, FL_SMEM>>>(Q, K, V, M_QQ, ATTN, N_, (long long)N_ * N_);
    mm_tf32<EPI_NONE><<<dim3(8, 32), 256, MM_SMEM>>>(ATTN, w_self_out, nullptr, PROJ, D_, D_);
    resid_gate_kernel<<<4194304 / 256, 256>>>(q_x, ADA + 2 * D_, PROJ, X);

    // ---- Pass 2: cross-attention ----
    ln_mod_kernel<<<BN_, 256>>>(X, w_ln_cross, ADA + 3 * D_, ADA + 4 * D_, XN);
    mm_tf32<EPI_NONE><<<dim3(8, 32), 256, MM_SMEM>>>(XN, w_qproj, nullptr, QKV, D_, D_);
    rope_q_kernel<<<4194304 / 256, 256>>>(QKV, cosb, sinb, QC);
    memln_kernel<<<B_ * M2_, 256>>>(h_content, h_obs, w_ln_mem, MEMLN);
    mm_tf32<EPI_NONE><<<dim3(16, 64), 256, MM_SMEM>>>(MEMLN, w_kvproj, nullptr, KV, D_, 2048);
    rope_split_kv<<<8388608 / 256, 256>>>(KV, cosb, sinb, KC, VC);
    flash_attn<<<dim3(8, H_, B_), 256, FL_SMEM>>>(QC, KC, VC, M_hyb, ATTN, M2_, (long long)N_ * M2_);
    mm_tf32<EPI_NONE><<<dim3(8, 32), 256, MM_SMEM>>>(ATTN, w_cross_out, nullptr, PROJ, D_, D_);
    resid_gate_kernel<<<4194304 / 256, 256>>>(X, ADA + 5 * D_, PROJ, X);

    // ---- Pass 3: MLP ----
    ln_mod_kernel<<<BN_, 256>>>(X, w_ln_mlp, ADA + 6 * D_, ADA + 7 * D_, XN);
    mm_tf32<EPI_GELU><<<dim3(32, 32), 256, MM_SMEM>>>(XN, w_mlp1, b_mlp1, HBUF, D_, 4096);
    mm_tf32<EPI_BIAS><<<dim3(8, 32), 256, MM_SMEM>>>(HBUF, w_mlp2, b_mlp2, PROJ, 4096, D_);
    resid_gate_kernel<<<4194304 / 256, 256>>>(X, ADA + 8 * D_, PROJ, out);
}